// round 12
// baseline (speedup 1.0000x reference)
#include <cuda_runtime.h>

// ---------------------------------------------------------------------------
// HAttention1D: b=4 h=8 n=8192 d=64, block=16, 9 levels (0..8).
// R11: pipelined fused01 THAT KEEPS 2 CTAs/SM (R10's failure was 1 CTA/SM):
//      - lvl1 pooling fused into the attn loops (no lvl1 smem, no pool phase)
//      - coarse Y/A read directly from L2 in phase C (no staging smem)
//      -> smem 113.3KB, cp.async double-buffer, 16 warps/SM.
//   K_A  hatt_lvl23  : orig->pool x4 in regs, attn lvl2-3, emit pooled 4/6/8.
//   K_T  hatt_tail   : ONE kernel, 352 CTAs: lvl4-5, lvl6-7, lvl8.
//   K_F  hatt_fused01: pipelined attn lvl0-1 + direct coarse + divide -> out.
// ---------------------------------------------------------------------------

#define BHN 32
#define N0  8192
#define DD  64
#define SD  68   // padded smem row stride in floats

typedef unsigned long long u64;

// ---- packed f32x2 helpers ----
__device__ __forceinline__ u64 pk2(float a, float b) {
    u64 r; asm("mov.b64 %0, {%1, %2};" : "=l"(r) : "f"(a), "f"(b)); return r;
}
__device__ __forceinline__ void up2(u64 v, float& a, float& b) {
    asm("mov.b64 {%0, %1}, %2;" : "=f"(a), "=f"(b) : "l"(v));
}
__device__ __forceinline__ u64 fma2(u64 a, u64 b, u64 c) {
    u64 r; asm("fma.rn.f32x2 %0, %1, %2, %3;" : "=l"(r) : "l"(a), "l"(b), "l"(c)); return r;
}
__device__ __forceinline__ u64 add2(u64 a, u64 b) {
    u64 r; asm("add.rn.f32x2 %0, %1, %2;" : "=l"(r) : "l"(a), "l"(b)); return r;
}
__device__ __forceinline__ u64 mul2(u64 a, u64 b) {
    u64 r; asm("mul.rn.f32x2 %0, %1, %2;" : "=l"(r) : "l"(a), "l"(b)); return r;
}

// ---- cp.async helpers ----
__device__ __forceinline__ unsigned s2u(const void* p) {
    unsigned a;
    asm("{ .reg .u64 t; cvta.to.shared.u64 t, %1; cvt.u32.u64 %0, t; }"
        : "=r"(a) : "l"(p));
    return a;
}
#define CPA16(dst, src) \
    asm volatile("cp.async.cg.shared.global [%0], [%1], 16;" :: "r"(dst), "l"(src) : "memory")
#define CPA_COMMIT() asm volatile("cp.async.commit_group;" ::: "memory")

// ---- scratch (device globals; no allocations allowed) ----
__device__ __align__(16) float g_Y23[(size_t)BHN * (N0 / 4) * DD];   // 16 MB
__device__ __align__(16) float g_A23[BHN * (N0 / 4)];
__device__ __align__(16) float g_q4[BHN * (N0 / 16) * DD];           // 4 MB ea
__device__ __align__(16) float g_k4[BHN * (N0 / 16) * DD];
__device__ __align__(16) float g_v4[BHN * (N0 / 16) * DD];
__device__ __align__(16) float g_Y45[BHN * (N0 / 16) * DD];
__device__ __align__(16) float g_A45[BHN * (N0 / 16)];
__device__ __align__(16) float g_q6[BHN * (N0 / 64) * DD];           // 1 MB ea
__device__ __align__(16) float g_k6[BHN * (N0 / 64) * DD];
__device__ __align__(16) float g_v6[BHN * (N0 / 64) * DD];
__device__ __align__(16) float g_Y67[BHN * (N0 / 64) * DD];
__device__ __align__(16) float g_A67[BHN * (N0 / 64)];
__device__ __align__(16) float g_q8[BHN * (N0 / 256) * DD];          // 256 KB ea
__device__ __align__(16) float g_k8[BHN * (N0 / 256) * DD];
__device__ __align__(16) float g_v8[BHN * (N0 / 256) * DD];
__device__ __align__(16) float g_Y8[BHN * (N0 / 256) * DD];
__device__ __align__(16) float g_A8[BHN * (N0 / 256)];

__device__ __forceinline__ float4 f4_scale(float4 a, float s) {
    return make_float4(a.x * s, a.y * s, a.z * s, a.w * s);
}
__device__ __forceinline__ float4 f4_add(float4 a, float4 b) {
    return make_float4(a.x + b.x, a.y + b.y, a.z + b.z, a.w + b.w);
}
__device__ __forceinline__ float4 f4_avg(float4 a, float4 b) {
    return make_float4((a.x + b.x) * 0.5f, (a.y + b.y) * 0.5f,
                       (a.z + b.z) * 0.5f, (a.w + b.w) * 0.5f);
}

// ---------------------------------------------------------------------------
// One warp: full 16x16 block attention. Lane (i, dg): query row i, d-half dg.
// sscale multiplies the raw dot products.
// ---------------------------------------------------------------------------
__device__ __forceinline__ float attn_block(
    const float* __restrict__ qB, const float* __restrict__ kB,
    const float* __restrict__ vB, int i, int dg, u64 yp[16], float sscale)
{
    const float* qr = qB + i * SD;
    const float* kr = kB + dg * 8 * SD;
    u64 acc[8];
#pragma unroll
    for (int jj = 0; jj < 8; jj++) acc[jj] = 0ull;
#pragma unroll
    for (int c4 = 0; c4 < 16; c4++) {
        ulonglong2 qv = *(const ulonglong2*)(qr + c4 * 4);
#pragma unroll
        for (int jj = 0; jj < 8; jj++) {
            ulonglong2 kv = *(const ulonglong2*)(kr + jj * SD + c4 * 4);
            acc[jj] = fma2(qv.x, kv.x, acc[jj]);
            acc[jj] = fma2(qv.y, kv.y, acc[jj]);
        }
    }
    float s[8];
#pragma unroll
    for (int jj = 0; jj < 8; jj++) {
        float lo, hi; up2(acc[jj], lo, hi);
        s[jj] = (lo + hi) * sscale;
    }
    float m = s[0];
#pragma unroll
    for (int jj = 1; jj < 8; jj++) m = fmaxf(m, s[jj]);
    m = fmaxf(m, __shfl_xor_sync(0xffffffffu, m, 16));
    float A[8];
    float rs = 0.f;
#pragma unroll
    for (int jj = 0; jj < 8; jj++) { A[jj] = __expf(s[jj] - m); rs += A[jj]; }
    rs += __shfl_xor_sync(0xffffffffu, rs, 16);
    float Af0[8], Af1[8];
#pragma unroll
    for (int jj = 0; jj < 8; jj++) {
        float o = __shfl_xor_sync(0xffffffffu, A[jj], 16);
        Af0[jj] = dg ? o : A[jj];
        Af1[jj] = dg ? A[jj] : o;
    }
#pragma unroll
    for (int cc = 0; cc < 16; cc++) yp[cc] = 0ull;
#pragma unroll
    for (int jj = 0; jj < 8; jj++) {
        u64 a0 = pk2(Af0[jj], Af0[jj]);
        u64 a1 = pk2(Af1[jj], Af1[jj]);
        const ulonglong2* vr0 = (const ulonglong2*)(vB + jj * SD + (dg << 5));
        const ulonglong2* vr1 = (const ulonglong2*)(vB + (8 + jj) * SD + (dg << 5));
#pragma unroll
        for (int cc = 0; cc < 8; cc++) {
            ulonglong2 v0 = vr0[cc];
            ulonglong2 v1 = vr1[cc];
            yp[2 * cc]     = fma2(a0, v0.x, yp[2 * cc]);
            yp[2 * cc + 1] = fma2(a0, v0.y, yp[2 * cc + 1]);
            yp[2 * cc]     = fma2(a1, v1.x, yp[2 * cc]);
            yp[2 * cc + 1] = fma2(a1, v1.y, yp[2 * cc + 1]);
        }
    }
    return rs;
}

// ---------------------------------------------------------------------------
// Pooled-pair variant: operates on RAW rows, pooling pairs inline.
// qB/kB/vB point at 32-raw-row blocks. lvl1 token j = raw rows 2j, 2j+1.
// S = (q_sum)·(k_sum) * sscale  with sscale = 0.125/4 (folds the two means).
// v side uses pair SUMS (reference sums v).
// ---------------------------------------------------------------------------
__device__ __forceinline__ float attn_block_p2(
    const float* __restrict__ qB, const float* __restrict__ kB,
    const float* __restrict__ vB, int i, int dg, u64 yp[16], float sscale)
{
    const float* qr = qB + (2 * i) * SD;
    const float* kr = kB + (dg * 16) * SD;
    u64 acc[8];
#pragma unroll
    for (int jj = 0; jj < 8; jj++) acc[jj] = 0ull;
#pragma unroll
    for (int c4 = 0; c4 < 16; c4++) {
        ulonglong2 qa = *(const ulonglong2*)(qr + c4 * 4);
        ulonglong2 qb2 = *(const ulonglong2*)(qr + SD + c4 * 4);
        u64 qx = add2(qa.x, qb2.x), qy = add2(qa.y, qb2.y);
#pragma unroll
        for (int jj = 0; jj < 8; jj++) {
            ulonglong2 ka = *(const ulonglong2*)(kr + (2 * jj) * SD + c4 * 4);
            ulonglong2 kb2 = *(const ulonglong2*)(kr + (2 * jj + 1) * SD + c4 * 4);
            acc[jj] = fma2(qx, add2(ka.x, kb2.x), acc[jj]);
            acc[jj] = fma2(qy, add2(ka.y, kb2.y), acc[jj]);
        }
    }
    float s[8];
#pragma unroll
    for (int jj = 0; jj < 8; jj++) {
        float lo, hi; up2(acc[jj], lo, hi);
        s[jj] = (lo + hi) * sscale;
    }
    float m = s[0];
#pragma unroll
    for (int jj = 1; jj < 8; jj++) m = fmaxf(m, s[jj]);
    m = fmaxf(m, __shfl_xor_sync(0xffffffffu, m, 16));
    float A[8];
    float rs = 0.f;
#pragma unroll
    for (int jj = 0; jj < 8; jj++) { A[jj] = __expf(s[jj] - m); rs += A[jj]; }
    rs += __shfl_xor_sync(0xffffffffu, rs, 16);
    float Af0[8], Af1[8];
#pragma unroll
    for (int jj = 0; jj < 8; jj++) {
        float o = __shfl_xor_sync(0xffffffffu, A[jj], 16);
        Af0[jj] = dg ? o : A[jj];
        Af1[jj] = dg ? A[jj] : o;
    }
#pragma unroll
    for (int cc = 0; cc < 16; cc++) yp[cc] = 0ull;
#pragma unroll
    for (int jj = 0; jj < 8; jj++) {
        u64 a0 = pk2(Af0[jj], Af0[jj]);
        u64 a1 = pk2(Af1[jj], Af1[jj]);
        const ulonglong2* va = (const ulonglong2*)(vB + (2 * jj) * SD + (dg << 5));
        const ulonglong2* vb_ = (const ulonglong2*)(vB + (2 * jj + 1) * SD + (dg << 5));
        const ulonglong2* vc = (const ulonglong2*)(vB + (16 + 2 * jj) * SD + (dg << 5));
        const ulonglong2* vd = (const ulonglong2*)(vB + (17 + 2 * jj) * SD + (dg << 5));
#pragma unroll
        for (int cc = 0; cc < 8; cc++) {
            u64 v0x = add2(va[cc].x, vb_[cc].x);
            u64 v0y = add2(va[cc].y, vb_[cc].y);
            u64 v1x = add2(vc[cc].x, vd[cc].x);
            u64 v1y = add2(vc[cc].y, vd[cc].y);
            yp[2 * cc]     = fma2(a0, v0x, yp[2 * cc]);
            yp[2 * cc]     = fma2(a1, v1x, yp[2 * cc]);
            yp[2 * cc + 1] = fma2(a0, v0y, yp[2 * cc + 1]);
            yp[2 * cc + 1] = fma2(a1, v1y, yp[2 * cc + 1]);
        }
    }
    return rs;
}

// ===========================================================================
// K_A: levels 2-3 from ORIGINAL inputs (pool x4 in registers during load).
// ===========================================================================
__global__ void __launch_bounds__(256, 2)
hatt_lvl23(const float* __restrict__ Q, const float* __restrict__ K,
           const float* __restrict__ V,
           float* __restrict__ Y23, float* __restrict__ A23,
           float* __restrict__ q4, float* __restrict__ k4, float* __restrict__ v4,
           float* __restrict__ q6, float* __restrict__ k6, float* __restrict__ v6,
           float* __restrict__ q8, float* __restrict__ k8, float* __restrict__ v8)
{
    extern __shared__ float sm[];
    float* s_q0 = sm;                     // 64*SD  (lvl2)
    float* s_k0 = s_q0 + 64 * SD;
    float* s_v0 = s_k0 + 64 * SD;
    float* s_q1 = s_v0 + 64 * SD;         // 32*SD  (lvl3)
    float* s_k1 = s_q1 + 32 * SD;
    float* s_v1 = s_k1 + 32 * SD;
    float* s_y1 = s_v1 + 32 * SD;         // 32*SD
    float* s_a1 = s_y1 + 32 * SD;         // 32
    float* s_p4q = s_a1 + 32;             // 16*SD (lvl4 stage)
    float* s_p4k = s_p4q + 16 * SD;
    float* s_p4v = s_p4k + 16 * SD;

    const int tid = threadIdx.x;
    const int bh = blockIdx.y;
    const int c = blockIdx.x;             // 0..31
    const size_t baseO = ((size_t)bh * N0 + (size_t)c * 256) * DD;

    {
        const int u = tid >> 4, cq = tid & 15, c4 = cq << 2;
        const float4* qf = (const float4*)(Q + baseO);
        const float4* kf = (const float4*)(K + baseO);
        const float4* vf = (const float4*)(V + baseO);
        const int i0 = (u << 8) + cq;
        float4 l2q[4], l2k[4], l2v[4];
#pragma unroll
        for (int g = 0; g < 4; g++) {
            int ib = i0 + (g << 6);
            float4 a0 = qf[ib], a1 = qf[ib + 16], a2 = qf[ib + 32], a3 = qf[ib + 48];
            l2q[g] = f4_scale(f4_avg(f4_avg(a0, a1), f4_avg(a2, a3)), 0.125f);
            float4 b0 = kf[ib], b1 = kf[ib + 16], b2 = kf[ib + 32], b3 = kf[ib + 48];
            l2k[g] = f4_avg(f4_avg(b0, b1), f4_avg(b2, b3));
            float4 d0 = vf[ib], d1 = vf[ib + 16], d2 = vf[ib + 32], d3 = vf[ib + 48];
            l2v[g] = f4_add(f4_add(d0, d1), f4_add(d2, d3));
        }
        const int r0 = (u << 2) * SD + c4;
#pragma unroll
        for (int g = 0; g < 4; g++) {
            *(float4*)(s_q0 + r0 + g * SD) = l2q[g];
            *(float4*)(s_k0 + r0 + g * SD) = l2k[g];
            *(float4*)(s_v0 + r0 + g * SD) = l2v[g];
        }
        float4 q3a = f4_avg(l2q[0], l2q[1]), q3b = f4_avg(l2q[2], l2q[3]);
        float4 k3a = f4_avg(l2k[0], l2k[1]), k3b = f4_avg(l2k[2], l2k[3]);
        float4 v3a = f4_add(l2v[0], l2v[1]), v3b = f4_add(l2v[2], l2v[3]);
        const int r1 = (u << 1) * SD + c4;
        *(float4*)(s_q1 + r1) = q3a;  *(float4*)(s_q1 + r1 + SD) = q3b;
        *(float4*)(s_k1 + r1) = k3a;  *(float4*)(s_k1 + r1 + SD) = k3b;
        *(float4*)(s_v1 + r1) = v3a;  *(float4*)(s_v1 + r1 + SD) = v3b;
        float4 q4r = f4_avg(q3a, q3b), k4r = f4_avg(k3a, k3b), v4r = f4_add(v3a, v3b);
        *(float4*)(s_p4q + u * SD + c4) = q4r;
        *(float4*)(s_p4k + u * SD + c4) = k4r;
        *(float4*)(s_p4v + u * SD + c4) = v4r;
        const size_t gi = ((size_t)(bh * 512 + c * 16 + u)) * 16 + cq;
        ((float4*)q4)[gi] = q4r; ((float4*)k4)[gi] = k4r; ((float4*)v4)[gi] = v4r;
    }
    __syncthreads();

    const int w = tid >> 5, lane = tid & 31, i = lane & 15, dg = lane >> 4;
    u64 yp[16];
    float rs = 0.f;
    if (w < 4) {
        int sb = w ^ 1;
        rs = attn_block(s_q0 + w * 16 * SD, s_k0 + sb * 16 * SD,
                        s_v0 + sb * 16 * SD, i, dg, yp, 1.0f);
    } else if (w < 6) {
        int qb = w - 4, sb = qb ^ 1;
        rs = attn_block(s_q1 + qb * 16 * SD, s_k1 + sb * 16 * SD,
                        s_v1 + sb * 16 * SD, i, dg, yp, 1.0f);
        float* yo = s_y1 + (qb * 16 + i) * SD + (dg << 5);
#pragma unroll
        for (int cc = 0; cc < 8; cc++)
            *(ulonglong2*)(yo + cc * 4) = make_ulonglong2(yp[2 * cc], yp[2 * cc + 1]);
        if (dg == 0) s_a1[qb * 16 + i] = rs;
    } else if (w == 6) {
#pragma unroll
        for (int it = 0; it < 2; it++) {
            int idx = (it << 5) + lane;
            int t = idx >> 4, cq = idx & 15, c4s = cq << 2;
            const float* pq = s_p4q + (t << 2) * SD + c4s;
            const float* pk = s_p4k + (t << 2) * SD + c4s;
            const float* pv = s_p4v + (t << 2) * SD + c4s;
            float4 r6q = f4_avg(f4_avg(*(const float4*)pq, *(const float4*)(pq + SD)),
                                f4_avg(*(const float4*)(pq + 2 * SD), *(const float4*)(pq + 3 * SD)));
            float4 r6k = f4_avg(f4_avg(*(const float4*)pk, *(const float4*)(pk + SD)),
                                f4_avg(*(const float4*)(pk + 2 * SD), *(const float4*)(pk + 3 * SD)));
            float4 r6v = f4_add(f4_add(*(const float4*)pv, *(const float4*)(pv + SD)),
                                f4_add(*(const float4*)(pv + 2 * SD), *(const float4*)(pv + 3 * SD)));
            const size_t gi = ((size_t)(bh * 128 + (c << 2) + t)) * 16 + cq;
            ((float4*)q6)[gi] = r6q; ((float4*)k6)[gi] = r6k; ((float4*)v6)[gi] = r6v;
        }
    } else {
        if (lane < 16) {
            int c4s = lane << 2;
            const size_t gi = ((size_t)(bh * 32 + c)) * 16 + lane;
            {
                float4 t5[8];
#pragma unroll
                for (int j = 0; j < 8; j++) {
                    const float* p = s_p4q + (2 * j) * SD + c4s;
                    t5[j] = f4_avg(*(const float4*)p, *(const float4*)(p + SD));
                }
                float4 t6a = f4_avg(t5[0], t5[1]), t6b = f4_avg(t5[2], t5[3]);
                float4 t6c = f4_avg(t5[4], t5[5]), t6d = f4_avg(t5[6], t5[7]);
                ((float4*)q8)[gi] = f4_avg(f4_avg(t6a, t6b), f4_avg(t6c, t6d));
            }
            {
                float4 t5[8];
#pragma unroll
                for (int j = 0; j < 8; j++) {
                    const float* p = s_p4k + (2 * j) * SD + c4s;
                    t5[j] = f4_avg(*(const float4*)p, *(const float4*)(p + SD));
                }
                float4 t6a = f4_avg(t5[0], t5[1]), t6b = f4_avg(t5[2], t5[3]);
                float4 t6c = f4_avg(t5[4], t5[5]), t6d = f4_avg(t5[6], t5[7]);
                ((float4*)k8)[gi] = f4_avg(f4_avg(t6a, t6b), f4_avg(t6c, t6d));
            }
            {
                float4 t5[8];
#pragma unroll
                for (int j = 0; j < 8; j++) {
                    const float* p = s_p4v + (2 * j) * SD + c4s;
                    t5[j] = f4_add(*(const float4*)p, *(const float4*)(p + SD));
                }
                float4 t6a = f4_add(t5[0], t5[1]), t6b = f4_add(t5[2], t5[3]);
                float4 t6c = f4_add(t5[4], t5[5]), t6d = f4_add(t5[6], t5[7]);
                ((float4*)v8)[gi] = f4_add(f4_add(t6a, t6b), f4_add(t6c, t6d));
            }
        }
    }
    __syncthreads();

    if (w < 4) {
        const int r = (w << 4) + i;
        const float* y1r = s_y1 + (r >> 1) * SD + (dg << 5);
        float* yg = Y23 + ((size_t)bh * 2048 + (size_t)c * 64 + r) * DD + (dg << 5);
#pragma unroll
        for (int cc = 0; cc < 8; cc++) {
            ulonglong2 u1 = *(const ulonglong2*)(y1r + cc * 4);
            *(ulonglong2*)(yg + cc * 4) =
                make_ulonglong2(add2(yp[2 * cc], u1.x), add2(yp[2 * cc + 1], u1.y));
        }
        if (dg == 0)
            A23[bh * 2048 + c * 64 + r] = rs + s_a1[r >> 1];
    }
}

// ===========================================================================
// K_T: fused tail. 352 CTAs: [0,256) lvl4-5; [256,320) lvl6-7; [320,352) lvl8.
// ===========================================================================
__global__ void __launch_bounds__(256, 2)
hatt_tail(const float* __restrict__ q4, const float* __restrict__ k4,
          const float* __restrict__ v4, float* __restrict__ Y45, float* __restrict__ A45,
          const float* __restrict__ q6, const float* __restrict__ k6,
          const float* __restrict__ v6, float* __restrict__ Y67, float* __restrict__ A67,
          const float* __restrict__ q8, const float* __restrict__ k8,
          const float* __restrict__ v8, float* __restrict__ Y8, float* __restrict__ A8)
{
    extern __shared__ float sm[];
    float* s_q0 = sm;
    float* s_k0 = s_q0 + 64 * SD;
    float* s_v0 = s_k0 + 64 * SD;
    float* s_q1 = s_v0 + 64 * SD;
    float* s_k1 = s_q1 + 32 * SD;
    float* s_v1 = s_k1 + 32 * SD;
    float* s_y1 = s_v1 + 32 * SD;
    float* s_a1 = s_y1 + 32 * SD;

    const int tid = threadIdx.x;
    const int bid = blockIdx.x;
    const int w = tid >> 5, lane = tid & 31, i = lane & 15, dg = lane >> 4;

    if (bid < 320) {
        const float *Q, *K, *V;
        float *Yd, *Ad;
        int ntok, c, bh;
        if (bid < 256) {
            bh = bid >> 3; c = bid & 7; ntok = 512;
            Q = q4; K = k4; V = v4; Yd = Y45; Ad = A45;
        } else {
            int b2 = bid - 256;
            bh = b2 >> 1; c = b2 & 1; ntok = 128;
            Q = q6; K = k6; V = v6; Yd = Y67; Ad = A67;
        }
        const size_t base = ((size_t)bh * ntok + (size_t)c * 64) * DD;

        {
            const int u = tid >> 4, cq = tid & 15, c4 = cq << 2;
            const float4* qf = (const float4*)(Q + base);
            const float4* kf = (const float4*)(K + base);
            const float4* vf = (const float4*)(V + base);
            const int i0 = (u << 6) + cq;
            float4 a0 = qf[i0], a1 = qf[i0 + 16], a2 = qf[i0 + 32], a3 = qf[i0 + 48];
            float4 b0 = kf[i0], b1 = kf[i0 + 16], b2 = kf[i0 + 32], b3 = kf[i0 + 48];
            float4 d0 = vf[i0], d1 = vf[i0 + 16], d2 = vf[i0 + 32], d3 = vf[i0 + 48];
            const int r0 = (u << 2) * SD + c4;
            *(float4*)(s_q0 + r0) = a0;           *(float4*)(s_q0 + r0 + SD) = a1;
            *(float4*)(s_q0 + r0 + 2 * SD) = a2;  *(float4*)(s_q0 + r0 + 3 * SD) = a3;
            *(float4*)(s_k0 + r0) = b0;           *(float4*)(s_k0 + r0 + SD) = b1;
            *(float4*)(s_k0 + r0 + 2 * SD) = b2;  *(float4*)(s_k0 + r0 + 3 * SD) = b3;
            *(float4*)(s_v0 + r0) = d0;           *(float4*)(s_v0 + r0 + SD) = d1;
            *(float4*)(s_v0 + r0 + 2 * SD) = d2;  *(float4*)(s_v0 + r0 + 3 * SD) = d3;
            const int r1 = (u << 1) * SD + c4;
            *(float4*)(s_q1 + r1) = f4_avg(a0, a1);  *(float4*)(s_q1 + r1 + SD) = f4_avg(a2, a3);
            *(float4*)(s_k1 + r1) = f4_avg(b0, b1);  *(float4*)(s_k1 + r1 + SD) = f4_avg(b2, b3);
            *(float4*)(s_v1 + r1) = f4_add(d0, d1);  *(float4*)(s_v1 + r1 + SD) = f4_add(d2, d3);
        }
        __syncthreads();

        u64 yp[16];
        float rs = 0.f;
        if (w < 4) {
            int sb = w ^ 1;
            rs = attn_block(s_q0 + w * 16 * SD, s_k0 + sb * 16 * SD,
                            s_v0 + sb * 16 * SD, i, dg, yp, 1.0f);
        } else if (w < 6) {
            int qb = w - 4, sb = qb ^ 1;
            rs = attn_block(s_q1 + qb * 16 * SD, s_k1 + sb * 16 * SD,
                            s_v1 + sb * 16 * SD, i, dg, yp, 1.0f);
            float* yo = s_y1 + (qb * 16 + i) * SD + (dg << 5);
#pragma unroll
            for (int cc = 0; cc < 8; cc++)
                *(ulonglong2*)(yo + cc * 4) = make_ulonglong2(yp[2 * cc], yp[2 * cc + 1]);
            if (dg == 0) s_a1[qb * 16 + i] = rs;
        }
        __syncthreads();

        if (w < 4) {
            const int r = (w << 4) + i;
            const float* y1r = s_y1 + (r >> 1) * SD + (dg << 5);
            float* yg = Yd + base + (size_t)r * DD + (dg << 5);
#pragma unroll
            for (int cc = 0; cc < 8; cc++) {
                ulonglong2 u1 = *(const ulonglong2*)(y1r + cc * 4);
                *(ulonglong2*)(yg + cc * 4) =
                    make_ulonglong2(add2(yp[2 * cc], u1.x), add2(yp[2 * cc + 1], u1.y));
            }
            if (dg == 0)
                Ad[bh * ntok + c * 64 + r] = rs + s_a1[r >> 1];
        }
    } else {
        const int bh = bid - 320;
        const size_t base = (size_t)bh * 32 * DD;
        const float4* qf = (const float4*)(q8 + base);
        const float4* kf = (const float4*)(k8 + base);
        const float4* vf = (const float4*)(v8 + base);
        for (int idx = tid; idx < 512; idx += 256) {
            int row = idx >> 4, c4 = (idx & 15) << 2;
            *(float4*)(s_q0 + row * SD + c4) = qf[idx];
            *(float4*)(s_k0 + row * SD + c4) = kf[idx];
            *(float4*)(s_v0 + row * SD + c4) = vf[idx];
        }
        __syncthreads();
        if (w < 2) {
            u64 yp[16];
            float rs = attn_block(s_q0 + w * 16 * SD, s_k0 + (w ^ 1) * 16 * SD,
                                  s_v0 + (w ^ 1) * 16 * SD, i, dg, yp, 1.0f);
            float* yg = Y8 + base + (size_t)((w << 4) + i) * DD + (dg << 5);
#pragma unroll
            for (int cc = 0; cc < 8; cc++)
                *(ulonglong2*)(yg + cc * 4) = make_ulonglong2(yp[2 * cc], yp[2 * cc + 1]);
            if (dg == 0) A8[bh * 32 + (w << 4) + i] = rs;
        }
    }
}

// ===========================================================================
// K_F: pipelined levels 0-1 + final combine. Grid (32, 32); each CTA does
// 4 chunks of 64 tokens with cp.async double-buffered raw q/k/v.
// lvl1 pooling fused into attn (no lvl1 smem/phase); coarse Y/A read straight
// from L2 in phase C. smem = 2*RBSZ + 32*SD + 32 = 113280 B -> 2 CTAs/SM.
// ===========================================================================
#define RBSZ (64 * SD * 3)

__global__ void __launch_bounds__(256, 2)
hatt_fused01(const float* __restrict__ Q, const float* __restrict__ K,
             const float* __restrict__ V, float* __restrict__ out,
             const float* __restrict__ Y23, const float* __restrict__ A23,
             const float* __restrict__ Y45, const float* __restrict__ A45,
             const float* __restrict__ Y67, const float* __restrict__ A67,
             const float* __restrict__ Y8, const float* __restrict__ A8)
{
    extern __shared__ float sm[];
    float* s_y1 = sm + 2 * RBSZ;          // 32*SD
    float* s_a1 = s_y1 + 32 * SD;         // 32

    const int tid = threadIdx.x;
    const int bh = blockIdx.y;
    const int gx = blockIdx.x;            // 0..31 -> chunks 4gx..4gx+3
    const size_t bhbase = (size_t)bh * N0 * DD;

    const unsigned smb = s2u(sm);
    const unsigned o_k = 64 * SD * 4, o_v = 128 * SD * 4;
    const int u = tid >> 4, cq = tid & 15, c4i = cq << 2;

    auto issue = [&](int c, int buf) {
        unsigned rb = smb + (unsigned)(buf * RBSZ * 4);
        size_t g0 = bhbase + (size_t)c * 64 * DD;
#pragma unroll
        for (int r = 0; r < 4; r++) {
            int row = (u << 2) + r;
            unsigned so = (unsigned)((row * SD + c4i) * 4);
            size_t go = g0 + (size_t)row * DD + c4i;
            CPA16(rb + so, Q + go);
            CPA16(rb + o_k + so, K + go);
            CPA16(rb + o_v + so, V + go);
        }
        CPA_COMMIT();
    };

    issue(4 * gx + 0, 0);
    issue(4 * gx + 1, 1);

    const int w = tid >> 5, lane = tid & 31, i = lane & 15, dg = lane >> 4;

    for (int t = 0; t < 4; t++) {
        const int c = 4 * gx + t;
        const int buf = t & 1;
        const float* rq = sm + buf * RBSZ;
        const float* rk = rq + 64 * SD;
        const float* rv = rk + 64 * SD;

        if (t < 3) { asm volatile("cp.async.wait_group 1;" ::: "memory"); }
        else       { asm volatile("cp.async.wait_group 0;" ::: "memory"); }
        __syncthreads();

        // ---- attention: w0-3 lvl0 (self), w4-5 lvl1 (inline pair-pool) ----
        u64 yp[16];
        float rs = 0.f;
        if (w < 4) {
            rs = attn_block(rq + w * 16 * SD, rk + w * 16 * SD,
                            rv + w * 16 * SD, i, dg, yp, 0.125f);
        } else if (w < 6) {
            int qb = w - 4, sb = qb ^ 1;
            rs = attn_block_p2(rq + qb * 32 * SD, rk + sb * 32 * SD,
                               rv + sb * 32 * SD, i, dg, yp, 0.03125f);
            float* yo = s_y1 + (qb * 16 + i) * SD + (dg << 5);
#pragma unroll
            for (int cc = 0; cc < 8; cc++)
                *(ulonglong2*)(yo + cc * 4) = make_ulonglong2(yp[2 * cc], yp[2 * cc + 1]);
            if (dg == 0) s_a1[qb * 16 + i] = rs;
        }
        __syncthreads();

        // prefetch chunk t+2 into the buffer just freed
        if (t < 2) issue(c + 2, buf);

        // ---- Phase C (w 0-3): combine all levels (coarse direct from L2) ----
        if (w < 4) {
            const int r = (w << 4) + i;
            float a = rs + s_a1[r >> 1]
                    + A23[bh * 2048 + c * 16 + (r >> 2)]
                    + A45[bh * 512 + c * 4 + w]
                    + A67[bh * 128 + c]
                    + A8[bh * 32 + (c >> 2)] + 1e-8f;
            float inv = 1.0f / a;
            u64 inv2 = pk2(inv, inv);
            const float* y1r = s_y1 + (r >> 1) * SD + (dg << 5);
            const float* g23 = Y23 + ((size_t)(bh * 2048 + c * 16 + (r >> 2))) * DD + (dg << 5);
            const float* g45 = Y45 + ((size_t)(bh * 512 + c * 4 + w)) * DD + (dg << 5);
            const float* g67 = Y67 + ((size_t)(bh * 128 + c)) * DD + (dg << 5);
            const float* g8p = Y8 + ((size_t)(bh * 32 + (c >> 2))) * DD + (dg << 5);
            float* yg = out + bhbase + ((size_t)c * 64 + r) * DD + (dg << 5);
#pragma unroll
            for (int cc = 0; cc < 8; cc++) {
                ulonglong2 u1 = *(const ulonglong2*)(y1r + cc * 4);
                ulonglong2 u2 = *(const ulonglong2*)(g23 + cc * 4);
                ulonglong2 u4 = *(const ulonglong2*)(g45 + cc * 4);
                ulonglong2 u6 = *(const ulonglong2*)(g67 + cc * 4);
                ulonglong2 u8v = *(const ulonglong2*)(g8p + cc * 4);
                u64 sx = add2(add2(yp[2 * cc], u1.x),
                              add2(add2(u2.x, u4.x), add2(u6.x, u8v.x)));
                u64 sy = add2(add2(yp[2 * cc + 1], u1.y),
                              add2(add2(u2.y, u4.y), add2(u6.y, u8v.y)));
                *(ulonglong2*)(yg + cc * 4) = make_ulonglong2(mul2(sx, inv2), mul2(sy, inv2));
            }
        }
    }
}

// ---------------------------------------------------------------------------
extern "C" void kernel_launch(void* const* d_in, const int* in_sizes, int n_in,
                              void* d_out, int out_size)
{
    const float* q = (const float*)d_in[0];
    const float* k = (const float*)d_in[1];
    const float* v = (const float*)d_in[2];
    float* out = (float*)d_out;
    (void)in_sizes; (void)n_in; (void)out_size;

    void *Y23, *A23, *q4, *k4, *v4, *Y45, *A45, *q6, *k6, *v6, *Y67, *A67;
    void *q8, *k8, *v8, *Y8, *A8;
    cudaGetSymbolAddress(&Y23, g_Y23);
    cudaGetSymbolAddress(&A23, g_A23);
    cudaGetSymbolAddress(&q4, g_q4);
    cudaGetSymbolAddress(&k4, g_k4);
    cudaGetSymbolAddress(&v4, g_v4);
    cudaGetSymbolAddress(&Y45, g_Y45);
    cudaGetSymbolAddress(&A45, g_A45);
    cudaGetSymbolAddress(&q6, g_q6);
    cudaGetSymbolAddress(&k6, g_k6);
    cudaGetSymbolAddress(&v6, g_v6);
    cudaGetSymbolAddress(&Y67, g_Y67);
    cudaGetSymbolAddress(&A67, g_A67);
    cudaGetSymbolAddress(&q8, g_q8);
    cudaGetSymbolAddress(&k8, g_k8);
    cudaGetSymbolAddress(&v8, g_v8);
    cudaGetSymbolAddress(&Y8, g_Y8);
    cudaGetSymbolAddress(&A8, g_A8);

    const int S23 = (64 * SD * 3 + 32 * SD * 4 + 32 + 16 * SD * 3) * (int)sizeof(float); // 100224
    const int ST  = (64 * SD * 3 + 32 * SD * 4 + 32) * (int)sizeof(float);               // 87168
    const int SF  = (2 * RBSZ + 32 * SD + 32) * (int)sizeof(float);                      // 113280
    cudaFuncSetAttribute(hatt_lvl23, cudaFuncAttributeMaxDynamicSharedMemorySize, S23);
    cudaFuncSetAttribute(hatt_tail, cudaFuncAttributeMaxDynamicSharedMemorySize, ST);
    cudaFuncSetAttribute(hatt_fused01, cudaFuncAttributeMaxDynamicSharedMemorySize, SF);

    // K_A: levels 2-3 from original (pool x4 in regs) + pooled lvl4/6/8 out.
    hatt_lvl23<<<dim3(32, 32), 256, S23>>>(
        q, k, v, (float*)Y23, (float*)A23,
        (float*)q4, (float*)k4, (float*)v4,
        (float*)q6, (float*)k6, (float*)v6,
        (float*)q8, (float*)k8, (float*)v8);

    // K_T: fused tail (levels 4-5, 6-7, 8) in one launch.
    hatt_tail<<<352, 256, ST>>>(
        (const float*)q4, (const float*)k4, (const float*)v4, (float*)Y45, (float*)A45,
        (const float*)q6, (const float*)k6, (const float*)v6, (float*)Y67, (float*)A67,
        (const float*)q8, (const float*)k8, (const float*)v8, (float*)Y8, (float*)A8);

    // K_F: pipelined levels 0-1 + combine + divide -> out.
    hatt_fused01<<<dim3(32, 32), 256, SF>>>(
        q, k, v, out,
        (const float*)Y23, (const float*)A23, (const float*)Y45, (const float*)A45,
        (const float*)Y67, (const float*)A67, (const float*)Y8, (const float*)A8);
}

// round 13
// speedup vs baseline: 1.1102x; 1.1102x over previous
#include <cuda_runtime.h>

// ---------------------------------------------------------------------------
// HAttention1D: b=4 h=8 n=8192 d=64, block=16, 9 levels (0..8).
// R12: exact R9 structure (best known: 162.5us) + wave-1 phase staggering:
//      co-resident CTA pairs (linear bids b, b+148) are offset by ~one
//      compute phase so one CTA's DRAM load overlaps the other's compute.
//   K_A  hatt_lvl23  : orig->pool x4 in regs, attn lvl2-3, emit pooled 4/6/8.
//   K_T  hatt_tail   : ONE kernel, 352 CTAs: lvl4-5, lvl6-7, lvl8.
//   K_F  hatt_fused01: attn lvl0-1 + staged coarse + divide -> out.
// ---------------------------------------------------------------------------

#define BHN 32
#define N0  8192
#define DD  64
#define SD  68   // padded smem row stride in floats

typedef unsigned long long u64;

// ---- packed f32x2 helpers ----
__device__ __forceinline__ u64 pk2(float a, float b) {
    u64 r; asm("mov.b64 %0, {%1, %2};" : "=l"(r) : "f"(a), "f"(b)); return r;
}
__device__ __forceinline__ void up2(u64 v, float& a, float& b) {
    asm("mov.b64 {%0, %1}, %2;" : "=f"(a), "=f"(b) : "l"(v));
}
__device__ __forceinline__ u64 fma2(u64 a, u64 b, u64 c) {
    u64 r; asm("fma.rn.f32x2 %0, %1, %2, %3;" : "=l"(r) : "l"(a), "l"(b), "l"(c)); return r;
}
__device__ __forceinline__ u64 add2(u64 a, u64 b) {
    u64 r; asm("add.rn.f32x2 %0, %1, %2;" : "=l"(r) : "l"(a), "l"(b)); return r;
}
__device__ __forceinline__ u64 mul2(u64 a, u64 b) {
    u64 r; asm("mul.rn.f32x2 %0, %1, %2;" : "=l"(r) : "l"(a), "l"(b)); return r;
}

// ---- wave-1 stagger: delay the second co-resident CTA (linear/148 odd) ----
__device__ __forceinline__ void stagger(int linear_bid, long long cycles) {
    if ((linear_bid / 148) & 1) {
        long long s = clock64();
        while (clock64() - s < cycles) { }
    }
}

// ---- scratch (device globals; no allocations allowed) ----
__device__ __align__(16) float g_Y23[(size_t)BHN * (N0 / 4) * DD];   // 16 MB
__device__ __align__(16) float g_A23[BHN * (N0 / 4)];
__device__ __align__(16) float g_q4[BHN * (N0 / 16) * DD];           // 4 MB ea
__device__ __align__(16) float g_k4[BHN * (N0 / 16) * DD];
__device__ __align__(16) float g_v4[BHN * (N0 / 16) * DD];
__device__ __align__(16) float g_Y45[BHN * (N0 / 16) * DD];
__device__ __align__(16) float g_A45[BHN * (N0 / 16)];
__device__ __align__(16) float g_q6[BHN * (N0 / 64) * DD];           // 1 MB ea
__device__ __align__(16) float g_k6[BHN * (N0 / 64) * DD];
__device__ __align__(16) float g_v6[BHN * (N0 / 64) * DD];
__device__ __align__(16) float g_Y67[BHN * (N0 / 64) * DD];
__device__ __align__(16) float g_A67[BHN * (N0 / 64)];
__device__ __align__(16) float g_q8[BHN * (N0 / 256) * DD];          // 256 KB ea
__device__ __align__(16) float g_k8[BHN * (N0 / 256) * DD];
__device__ __align__(16) float g_v8[BHN * (N0 / 256) * DD];
__device__ __align__(16) float g_Y8[BHN * (N0 / 256) * DD];
__device__ __align__(16) float g_A8[BHN * (N0 / 256)];

__device__ __forceinline__ float4 f4_scale(float4 a, float s) {
    return make_float4(a.x * s, a.y * s, a.z * s, a.w * s);
}
__device__ __forceinline__ float4 f4_add(float4 a, float4 b) {
    return make_float4(a.x + b.x, a.y + b.y, a.z + b.z, a.w + b.w);
}
__device__ __forceinline__ float4 f4_avg(float4 a, float4 b) {
    return make_float4((a.x + b.x) * 0.5f, (a.y + b.y) * 0.5f,
                       (a.z + b.z) * 0.5f, (a.w + b.w) * 0.5f);
}

// ---------------------------------------------------------------------------
// One warp: full 16x16 block attention. Lane (i, dg): query row i, d-half dg.
// ---------------------------------------------------------------------------
__device__ __forceinline__ float attn_block(
    const float* __restrict__ qB, const float* __restrict__ kB,
    const float* __restrict__ vB, int i, int dg, u64 yp[16])
{
    const float* qr = qB + i * SD;
    const float* kr = kB + dg * 8 * SD;
    u64 acc[8];
#pragma unroll
    for (int jj = 0; jj < 8; jj++) acc[jj] = 0ull;
#pragma unroll
    for (int c4 = 0; c4 < 16; c4++) {
        ulonglong2 qv = *(const ulonglong2*)(qr + c4 * 4);
#pragma unroll
        for (int jj = 0; jj < 8; jj++) {
            ulonglong2 kv = *(const ulonglong2*)(kr + jj * SD + c4 * 4);
            acc[jj] = fma2(qv.x, kv.x, acc[jj]);
            acc[jj] = fma2(qv.y, kv.y, acc[jj]);
        }
    }
    float s[8];
#pragma unroll
    for (int jj = 0; jj < 8; jj++) { float lo, hi; up2(acc[jj], lo, hi); s[jj] = lo + hi; }
    float m = s[0];
#pragma unroll
    for (int jj = 1; jj < 8; jj++) m = fmaxf(m, s[jj]);
    m = fmaxf(m, __shfl_xor_sync(0xffffffffu, m, 16));
    float A[8];
    float rs = 0.f;
#pragma unroll
    for (int jj = 0; jj < 8; jj++) { A[jj] = __expf(s[jj] - m); rs += A[jj]; }
    rs += __shfl_xor_sync(0xffffffffu, rs, 16);
    float Af0[8], Af1[8];
#pragma unroll
    for (int jj = 0; jj < 8; jj++) {
        float o = __shfl_xor_sync(0xffffffffu, A[jj], 16);
        Af0[jj] = dg ? o : A[jj];
        Af1[jj] = dg ? A[jj] : o;
    }
#pragma unroll
    for (int cc = 0; cc < 16; cc++) yp[cc] = 0ull;
#pragma unroll
    for (int jj = 0; jj < 8; jj++) {
        u64 a0 = pk2(Af0[jj], Af0[jj]);
        u64 a1 = pk2(Af1[jj], Af1[jj]);
        const ulonglong2* vr0 = (const ulonglong2*)(vB + jj * SD + (dg << 5));
        const ulonglong2* vr1 = (const ulonglong2*)(vB + (8 + jj) * SD + (dg << 5));
#pragma unroll
        for (int cc = 0; cc < 8; cc++) {
            ulonglong2 v0 = vr0[cc];
            ulonglong2 v1 = vr1[cc];
            yp[2 * cc]     = fma2(a0, v0.x, yp[2 * cc]);
            yp[2 * cc + 1] = fma2(a0, v0.y, yp[2 * cc + 1]);
            yp[2 * cc]     = fma2(a1, v1.x, yp[2 * cc]);
            yp[2 * cc + 1] = fma2(a1, v1.y, yp[2 * cc + 1]);
        }
    }
    return rs;
}

// ===========================================================================
// K_A: levels 2-3 from ORIGINAL inputs (pool x4 in registers during load).
// Chunk = 256 orig tokens = 64 lvl2 tokens. Warps 0-3: lvl2 blocks (flip);
// 4-5: lvl3 blocks (flip); 6: lvl6 pool-out; 7: lvl8 pool-out.
// ===========================================================================
__global__ void __launch_bounds__(256, 2)
hatt_lvl23(const float* __restrict__ Q, const float* __restrict__ K,
           const float* __restrict__ V,
           float* __restrict__ Y23, float* __restrict__ A23,
           float* __restrict__ q4, float* __restrict__ k4, float* __restrict__ v4,
           float* __restrict__ q6, float* __restrict__ k6, float* __restrict__ v6,
           float* __restrict__ q8, float* __restrict__ k8, float* __restrict__ v8)
{
    extern __shared__ float sm[];
    float* s_q0 = sm;                     // 64*SD  (lvl2)
    float* s_k0 = s_q0 + 64 * SD;
    float* s_v0 = s_k0 + 64 * SD;
    float* s_q1 = s_v0 + 64 * SD;         // 32*SD  (lvl3)
    float* s_k1 = s_q1 + 32 * SD;
    float* s_v1 = s_k1 + 32 * SD;
    float* s_y1 = s_v1 + 32 * SD;         // 32*SD
    float* s_a1 = s_y1 + 32 * SD;         // 32
    float* s_p4q = s_a1 + 32;             // 16*SD (lvl4 stage)
    float* s_p4k = s_p4q + 16 * SD;
    float* s_p4v = s_p4k + 16 * SD;

    const int tid = threadIdx.x;
    const int bh = blockIdx.y;
    const int c = blockIdx.x;             // 0..31
    const size_t baseO = ((size_t)bh * N0 + (size_t)c * 256) * DD;

    stagger(bh * 32 + c, 14000);          // ~ one compute phase @ ~1.8GHz

    // ---- Phase 1: each thread loads 16 orig rows at one f4-col, pools ----
    {
        const int u = tid >> 4, cq = tid & 15, c4 = cq << 2;
        const float4* qf = (const float4*)(Q + baseO);
        const float4* kf = (const float4*)(K + baseO);
        const float4* vf = (const float4*)(V + baseO);
        const int i0 = (u << 8) + cq;
        float4 l2q[4], l2k[4], l2v[4];
#pragma unroll
        for (int g = 0; g < 4; g++) {
            int ib = i0 + (g << 6);
            float4 a0 = qf[ib], a1 = qf[ib + 16], a2 = qf[ib + 32], a3 = qf[ib + 48];
            l2q[g] = f4_scale(f4_avg(f4_avg(a0, a1), f4_avg(a2, a3)), 0.125f);
            float4 b0 = kf[ib], b1 = kf[ib + 16], b2 = kf[ib + 32], b3 = kf[ib + 48];
            l2k[g] = f4_avg(f4_avg(b0, b1), f4_avg(b2, b3));
            float4 d0 = vf[ib], d1 = vf[ib + 16], d2 = vf[ib + 32], d3 = vf[ib + 48];
            l2v[g] = f4_add(f4_add(d0, d1), f4_add(d2, d3));
        }
        const int r0 = (u << 2) * SD + c4;
#pragma unroll
        for (int g = 0; g < 4; g++) {
            *(float4*)(s_q0 + r0 + g * SD) = l2q[g];
            *(float4*)(s_k0 + r0 + g * SD) = l2k[g];
            *(float4*)(s_v0 + r0 + g * SD) = l2v[g];
        }
        float4 q3a = f4_avg(l2q[0], l2q[1]), q3b = f4_avg(l2q[2], l2q[3]);
        float4 k3a = f4_avg(l2k[0], l2k[1]), k3b = f4_avg(l2k[2], l2k[3]);
        float4 v3a = f4_add(l2v[0], l2v[1]), v3b = f4_add(l2v[2], l2v[3]);
        const int r1 = (u << 1) * SD + c4;
        *(float4*)(s_q1 + r1) = q3a;  *(float4*)(s_q1 + r1 + SD) = q3b;
        *(float4*)(s_k1 + r1) = k3a;  *(float4*)(s_k1 + r1 + SD) = k3b;
        *(float4*)(s_v1 + r1) = v3a;  *(float4*)(s_v1 + r1 + SD) = v3b;
        float4 q4r = f4_avg(q3a, q3b), k4r = f4_avg(k3a, k3b), v4r = f4_add(v3a, v3b);
        *(float4*)(s_p4q + u * SD + c4) = q4r;
        *(float4*)(s_p4k + u * SD + c4) = k4r;
        *(float4*)(s_p4v + u * SD + c4) = v4r;
        const size_t gi = ((size_t)(bh * 512 + c * 16 + u)) * 16 + cq;
        ((float4*)q4)[gi] = q4r; ((float4*)k4)[gi] = k4r; ((float4*)v4)[gi] = v4r;
    }
    __syncthreads();

    const int w = tid >> 5, lane = tid & 31, i = lane & 15, dg = lane >> 4;
    u64 yp[16];
    float rs = 0.f;
    if (w < 4) {
        int sb = w ^ 1;
        rs = attn_block(s_q0 + w * 16 * SD, s_k0 + sb * 16 * SD,
                        s_v0 + sb * 16 * SD, i, dg, yp);
    } else if (w < 6) {
        int qb = w - 4, sb = qb ^ 1;
        rs = attn_block(s_q1 + qb * 16 * SD, s_k1 + sb * 16 * SD,
                        s_v1 + sb * 16 * SD, i, dg, yp);
        float* yo = s_y1 + (qb * 16 + i) * SD + (dg << 5);
#pragma unroll
        for (int cc = 0; cc < 8; cc++)
            *(ulonglong2*)(yo + cc * 4) = make_ulonglong2(yp[2 * cc], yp[2 * cc + 1]);
        if (dg == 0) s_a1[qb * 16 + i] = rs;
    } else if (w == 6) {
        // lvl6 pool-out: 4 rows x 16 cols from the 16 staged lvl4 rows
#pragma unroll
        for (int it = 0; it < 2; it++) {
            int idx = (it << 5) + lane;
            int t = idx >> 4, cq = idx & 15, c4s = cq << 2;
            const float* pq = s_p4q + (t << 2) * SD + c4s;
            const float* pk = s_p4k + (t << 2) * SD + c4s;
            const float* pv = s_p4v + (t << 2) * SD + c4s;
            float4 r6q = f4_avg(f4_avg(*(const float4*)pq, *(const float4*)(pq + SD)),
                                f4_avg(*(const float4*)(pq + 2 * SD), *(const float4*)(pq + 3 * SD)));
            float4 r6k = f4_avg(f4_avg(*(const float4*)pk, *(const float4*)(pk + SD)),
                                f4_avg(*(const float4*)(pk + 2 * SD), *(const float4*)(pk + 3 * SD)));
            float4 r6v = f4_add(f4_add(*(const float4*)pv, *(const float4*)(pv + SD)),
                                f4_add(*(const float4*)(pv + 2 * SD), *(const float4*)(pv + 3 * SD)));
            const size_t gi = ((size_t)(bh * 128 + (c << 2) + t)) * 16 + cq;
            ((float4*)q6)[gi] = r6q; ((float4*)k6)[gi] = r6k; ((float4*)v6)[gi] = r6v;
        }
    } else {
        // lvl8 pool-out: 1 row per chunk; pairwise tree over 16 lvl4 rows.
        if (lane < 16) {
            int c4s = lane << 2;
            const size_t gi = ((size_t)(bh * 32 + c)) * 16 + lane;
            {
                float4 t5[8];
#pragma unroll
                for (int j = 0; j < 8; j++) {
                    const float* p = s_p4q + (2 * j) * SD + c4s;
                    t5[j] = f4_avg(*(const float4*)p, *(const float4*)(p + SD));
                }
                float4 t6a = f4_avg(t5[0], t5[1]), t6b = f4_avg(t5[2], t5[3]);
                float4 t6c = f4_avg(t5[4], t5[5]), t6d = f4_avg(t5[6], t5[7]);
                ((float4*)q8)[gi] = f4_avg(f4_avg(t6a, t6b), f4_avg(t6c, t6d));
            }
            {
                float4 t5[8];
#pragma unroll
                for (int j = 0; j < 8; j++) {
                    const float* p = s_p4k + (2 * j) * SD + c4s;
                    t5[j] = f4_avg(*(const float4*)p, *(const float4*)(p + SD));
                }
                float4 t6a = f4_avg(t5[0], t5[1]), t6b = f4_avg(t5[2], t5[3]);
                float4 t6c = f4_avg(t5[4], t5[5]), t6d = f4_avg(t5[6], t5[7]);
                ((float4*)k8)[gi] = f4_avg(f4_avg(t6a, t6b), f4_avg(t6c, t6d));
            }
            {
                float4 t5[8];
#pragma unroll
                for (int j = 0; j < 8; j++) {
                    const float* p = s_p4v + (2 * j) * SD + c4s;
                    t5[j] = f4_add(*(const float4*)p, *(const float4*)(p + SD));
                }
                float4 t6a = f4_add(t5[0], t5[1]), t6b = f4_add(t5[2], t5[3]);
                float4 t6c = f4_add(t5[4], t5[5]), t6d = f4_add(t5[6], t5[7]);
                ((float4*)v8)[gi] = f4_add(f4_add(t6a, t6b), f4_add(t6c, t6d));
            }
        }
    }
    __syncthreads();

    if (w < 4) {
        const int r = (w << 4) + i;
        const float* y1r = s_y1 + (r >> 1) * SD + (dg << 5);
        float* yg = Y23 + ((size_t)bh * 2048 + (size_t)c * 64 + r) * DD + (dg << 5);
#pragma unroll
        for (int cc = 0; cc < 8; cc++) {
            ulonglong2 u1 = *(const ulonglong2*)(y1r + cc * 4);
            *(ulonglong2*)(yg + cc * 4) =
                make_ulonglong2(add2(yp[2 * cc], u1.x), add2(yp[2 * cc + 1], u1.y));
        }
        if (dg == 0)
            A23[bh * 2048 + c * 64 + r] = rs + s_a1[r >> 1];
    }
}

// ===========================================================================
// K_T: fused tail. 352 CTAs: [0,256) lvl4-5; [256,320) lvl6-7; [320,352) lvl8.
// ===========================================================================
__global__ void __launch_bounds__(256, 2)
hatt_tail(const float* __restrict__ q4, const float* __restrict__ k4,
          const float* __restrict__ v4, float* __restrict__ Y45, float* __restrict__ A45,
          const float* __restrict__ q6, const float* __restrict__ k6,
          const float* __restrict__ v6, float* __restrict__ Y67, float* __restrict__ A67,
          const float* __restrict__ q8, const float* __restrict__ k8,
          const float* __restrict__ v8, float* __restrict__ Y8, float* __restrict__ A8)
{
    extern __shared__ float sm[];
    float* s_q0 = sm;
    float* s_k0 = s_q0 + 64 * SD;
    float* s_v0 = s_k0 + 64 * SD;
    float* s_q1 = s_v0 + 64 * SD;
    float* s_k1 = s_q1 + 32 * SD;
    float* s_v1 = s_k1 + 32 * SD;
    float* s_y1 = s_v1 + 32 * SD;
    float* s_a1 = s_y1 + 32 * SD;

    const int tid = threadIdx.x;
    const int bid = blockIdx.x;
    const int w = tid >> 5, lane = tid & 31, i = lane & 15, dg = lane >> 4;

    if (bid < 320) {
        const float *Q, *K, *V;
        float *Yd, *Ad;
        int ntok, c, bh;
        if (bid < 256) {
            bh = bid >> 3; c = bid & 7; ntok = 512;
            Q = q4; K = k4; V = v4; Yd = Y45; Ad = A45;
        } else {
            int b2 = bid - 256;
            bh = b2 >> 1; c = b2 & 1; ntok = 128;
            Q = q6; K = k6; V = v6; Yd = Y67; Ad = A67;
        }
        const size_t base = ((size_t)bh * ntok + (size_t)c * 64) * DD;

        {
            const int u = tid >> 4, cq = tid & 15, c4 = cq << 2;
            const float4* qf = (const float4*)(Q + base);
            const float4* kf = (const float4*)(K + base);
            const float4* vf = (const float4*)(V + base);
            const int i0 = (u << 6) + cq;
            float4 a0 = qf[i0], a1 = qf[i0 + 16], a2 = qf[i0 + 32], a3 = qf[i0 + 48];
            float4 b0 = kf[i0], b1 = kf[i0 + 16], b2 = kf[i0 + 32], b3 = kf[i0 + 48];
            float4 d0 = vf[i0], d1 = vf[i0 + 16], d2 = vf[i0 + 32], d3 = vf[i0 + 48];
            const int r0 = (u << 2) * SD + c4;
            *(float4*)(s_q0 + r0) = a0;           *(float4*)(s_q0 + r0 + SD) = a1;
            *(float4*)(s_q0 + r0 + 2 * SD) = a2;  *(float4*)(s_q0 + r0 + 3 * SD) = a3;
            *(float4*)(s_k0 + r0) = b0;           *(float4*)(s_k0 + r0 + SD) = b1;
            *(float4*)(s_k0 + r0 + 2 * SD) = b2;  *(float4*)(s_k0 + r0 + 3 * SD) = b3;
            *(float4*)(s_v0 + r0) = d0;           *(float4*)(s_v0 + r0 + SD) = d1;
            *(float4*)(s_v0 + r0 + 2 * SD) = d2;  *(float4*)(s_v0 + r0 + 3 * SD) = d3;
            const int r1 = (u << 1) * SD + c4;
            *(float4*)(s_q1 + r1) = f4_avg(a0, a1);  *(float4*)(s_q1 + r1 + SD) = f4_avg(a2, a3);
            *(float4*)(s_k1 + r1) = f4_avg(b0, b1);  *(float4*)(s_k1 + r1 + SD) = f4_avg(b2, b3);
            *(float4*)(s_v1 + r1) = f4_add(d0, d1);  *(float4*)(s_v1 + r1 + SD) = f4_add(d2, d3);
        }
        __syncthreads();

        u64 yp[16];
        float rs = 0.f;
        if (w < 4) {
            int sb = w ^ 1;
            rs = attn_block(s_q0 + w * 16 * SD, s_k0 + sb * 16 * SD,
                            s_v0 + sb * 16 * SD, i, dg, yp);
        } else if (w < 6) {
            int qb = w - 4, sb = qb ^ 1;
            rs = attn_block(s_q1 + qb * 16 * SD, s_k1 + sb * 16 * SD,
                            s_v1 + sb * 16 * SD, i, dg, yp);
            float* yo = s_y1 + (qb * 16 + i) * SD + (dg << 5);
#pragma unroll
            for (int cc = 0; cc < 8; cc++)
                *(ulonglong2*)(yo + cc * 4) = make_ulonglong2(yp[2 * cc], yp[2 * cc + 1]);
            if (dg == 0) s_a1[qb * 16 + i] = rs;
        }
        __syncthreads();

        if (w < 4) {
            const int r = (w << 4) + i;
            const float* y1r = s_y1 + (r >> 1) * SD + (dg << 5);
            float* yg = Yd + base + (size_t)r * DD + (dg << 5);
#pragma unroll
            for (int cc = 0; cc < 8; cc++) {
                ulonglong2 u1 = *(const ulonglong2*)(y1r + cc * 4);
                *(ulonglong2*)(yg + cc * 4) =
                    make_ulonglong2(add2(yp[2 * cc], u1.x), add2(yp[2 * cc + 1], u1.y));
            }
            if (dg == 0)
                Ad[bh * ntok + c * 64 + r] = rs + s_a1[r >> 1];
        }
    } else {
        const int bh = bid - 320;
        const size_t base = (size_t)bh * 32 * DD;
        const float4* qf = (const float4*)(q8 + base);
        const float4* kf = (const float4*)(k8 + base);
        const float4* vf = (const float4*)(v8 + base);
        for (int idx = tid; idx < 512; idx += 256) {
            int row = idx >> 4, c4 = (idx & 15) << 2;
            *(float4*)(s_q0 + row * SD + c4) = qf[idx];
            *(float4*)(s_k0 + row * SD + c4) = kf[idx];
            *(float4*)(s_v0 + row * SD + c4) = vf[idx];
        }
        __syncthreads();
        if (w < 2) {
            u64 yp[16];
            float rs = attn_block(s_q0 + w * 16 * SD, s_k0 + (w ^ 1) * 16 * SD,
                                  s_v0 + (w ^ 1) * 16 * SD, i, dg, yp);
            float* yg = Y8 + base + (size_t)((w << 4) + i) * DD + (dg << 5);
#pragma unroll
            for (int cc = 0; cc < 8; cc++)
                *(ulonglong2*)(yg + cc * 4) = make_ulonglong2(yp[2 * cc], yp[2 * cc + 1]);
            if (dg == 0) A8[bh * 32 + (w << 4) + i] = rs;
        }
    }
}

// ===========================================================================
// K_F: levels 0-1 + final combine. Warps 6/7 stage coarse Y/A into smem
// during the attention phase; Phase C sums all levels, divides, writes out.
// ===========================================================================
__global__ void __launch_bounds__(256, 2)
hatt_fused01(const float* __restrict__ Q, const float* __restrict__ K,
             const float* __restrict__ V, float* __restrict__ out,
             const float* __restrict__ Y23, const float* __restrict__ A23,
             const float* __restrict__ Y45, const float* __restrict__ A45,
             const float* __restrict__ Y67, const float* __restrict__ A67,
             const float* __restrict__ Y8, const float* __restrict__ A8)
{
    extern __shared__ float sm[];
    float* s_q0 = sm;                     // 64*SD
    float* s_k0 = s_q0 + 64 * SD;
    float* s_v0 = s_k0 + 64 * SD;
    float* s_q1 = s_v0 + 64 * SD;         // 32*SD
    float* s_k1 = s_q1 + 32 * SD;
    float* s_v1 = s_k1 + 32 * SD;
    float* s_y1 = s_v1 + 32 * SD;         // 32*SD
    float* s_a1 = s_y1 + 32 * SD;         // 32
    float* s_c = s_a1 + 32;               // 22*SD coarse Y stage
    float* s_ca = s_c + 22 * SD;          // 22 coarse A stage

    const int tid = threadIdx.x;
    const int bh = blockIdx.y;
    const int c = blockIdx.x;             // 0..127
    const size_t base = ((size_t)bh * N0 + (size_t)c * 64) * DD;

    stagger(bh * 128 + c, 6500);          // ~ one compute phase

    // ---- Phase 1: load 64 orig rows (scaled q) + pool lvl1 locally ----
    {
        const int u = tid >> 4, cq = tid & 15, c4 = cq << 2;
        const float4* qf = (const float4*)(Q + base);
        const float4* kf = (const float4*)(K + base);
        const float4* vf = (const float4*)(V + base);
        const int i0 = (u << 6) + cq;
        float4 a0 = f4_scale(qf[i0], 0.125f), a1 = f4_scale(qf[i0 + 16], 0.125f);
        float4 a2 = f4_scale(qf[i0 + 32], 0.125f), a3 = f4_scale(qf[i0 + 48], 0.125f);
        float4 b0 = kf[i0], b1 = kf[i0 + 16], b2 = kf[i0 + 32], b3 = kf[i0 + 48];
        float4 d0 = vf[i0], d1 = vf[i0 + 16], d2 = vf[i0 + 32], d3 = vf[i0 + 48];
        const int r0 = (u << 2) * SD + c4;
        *(float4*)(s_q0 + r0) = a0;           *(float4*)(s_q0 + r0 + SD) = a1;
        *(float4*)(s_q0 + r0 + 2 * SD) = a2;  *(float4*)(s_q0 + r0 + 3 * SD) = a3;
        *(float4*)(s_k0 + r0) = b0;           *(float4*)(s_k0 + r0 + SD) = b1;
        *(float4*)(s_k0 + r0 + 2 * SD) = b2;  *(float4*)(s_k0 + r0 + 3 * SD) = b3;
        *(float4*)(s_v0 + r0) = d0;           *(float4*)(s_v0 + r0 + SD) = d1;
        *(float4*)(s_v0 + r0 + 2 * SD) = d2;  *(float4*)(s_v0 + r0 + 3 * SD) = d3;
        const int r1 = (u << 1) * SD + c4;
        *(float4*)(s_q1 + r1) = f4_avg(a0, a1);  *(float4*)(s_q1 + r1 + SD) = f4_avg(a2, a3);
        *(float4*)(s_k1 + r1) = f4_avg(b0, b1);  *(float4*)(s_k1 + r1 + SD) = f4_avg(b2, b3);
        *(float4*)(s_v1 + r1) = f4_add(d0, d1);  *(float4*)(s_v1 + r1 + SD) = f4_add(d2, d3);
    }
    __syncthreads();

    const int w = tid >> 5, lane = tid & 31, i = lane & 15, dg = lane >> 4;
    u64 yp[16];
    float rs = 0.f;
    if (w < 4) {
        // level 0: SELF-attention (no flip)
        rs = attn_block(s_q0 + w * 16 * SD, s_k0 + w * 16 * SD,
                        s_v0 + w * 16 * SD, i, dg, yp);
    } else if (w < 6) {
        int qb = w - 4, sb = qb ^ 1;
        rs = attn_block(s_q1 + qb * 16 * SD, s_k1 + sb * 16 * SD,
                        s_v1 + sb * 16 * SD, i, dg, yp);
        float* yo = s_y1 + (qb * 16 + i) * SD + (dg << 5);
#pragma unroll
        for (int cc = 0; cc < 8; cc++)
            *(ulonglong2*)(yo + cc * 4) = make_ulonglong2(yp[2 * cc], yp[2 * cc + 1]);
        if (dg == 0) s_a1[qb * 16 + i] = rs;
    } else if (w == 6) {
        // stage Y23: 16 rows (rows 0-15 of s_c)
        const float4* y23f = (const float4*)Y23;
#pragma unroll
        for (int it = 0; it < 8; it++) {
            int idx = (it << 5) + lane;
            int t = idx >> 4, cq = idx & 15;
            *(float4*)(s_c + t * SD + (cq << 2)) =
                y23f[((size_t)bh * 2048 + (size_t)c * 16 + t) * 16 + cq];
        }
    } else {
        // w==7: stage Y45 (rows 16-19), Y67 (20), Y8 (21), all coarse A's
        const float4* y45f = (const float4*)Y45;
#pragma unroll
        for (int it = 0; it < 2; it++) {
            int idx = (it << 5) + lane;
            int t = idx >> 4, cq = idx & 15;
            *(float4*)(s_c + (16 + t) * SD + (cq << 2)) =
                y45f[((size_t)bh * 512 + (size_t)c * 4 + t) * 16 + cq];
        }
        if (lane < 16) {
            *(float4*)(s_c + 20 * SD + (lane << 2)) =
                ((const float4*)Y67)[((size_t)bh * 128 + c) * 16 + lane];
            *(float4*)(s_c + 21 * SD + (lane << 2)) =
                ((const float4*)Y8)[((size_t)bh * 32 + (c >> 2)) * 16 + lane];
            s_ca[lane] = A23[bh * 2048 + c * 16 + lane];
        }
        if (lane < 4) s_ca[16 + lane] = A45[bh * 512 + c * 4 + lane];
        if (lane == 0) {
            s_ca[20] = A67[bh * 128 + c];
            s_ca[21] = A8[bh * 32 + (c >> 2)];
        }
    }
    __syncthreads();

    // ---- Phase C (w 0-3): sum all levels, divide, write out ----
    if (w < 4) {
        const int r = (w << 4) + i;
        float a = rs + s_a1[r >> 1] + s_ca[r >> 2] + s_ca[16 + (r >> 4)]
                + s_ca[20] + s_ca[21] + 1e-8f;
        float inv = 1.0f / a;
        u64 inv2 = pk2(inv, inv);
        const float* y1r = s_y1 + (r >> 1) * SD + (dg << 5);
        const float* c2p = s_c + (r >> 2) * SD + (dg << 5);
        const float* c4p = s_c + (16 + (r >> 4)) * SD + (dg << 5);
        const float* c6p = s_c + 20 * SD + (dg << 5);
        const float* c8p = s_c + 21 * SD + (dg << 5);
        float* yg = out + base + (size_t)r * DD + (dg << 5);
#pragma unroll
        for (int cc = 0; cc < 8; cc++) {
            ulonglong2 u1 = *(const ulonglong2*)(y1r + cc * 4);
            ulonglong2 u2 = *(const ulonglong2*)(c2p + cc * 4);
            ulonglong2 u4 = *(const ulonglong2*)(c4p + cc * 4);
            ulonglong2 u6 = *(const ulonglong2*)(c6p + cc * 4);
            ulonglong2 u8 = *(const ulonglong2*)(c8p + cc * 4);
            u64 sx = add2(add2(yp[2 * cc], u1.x),
                          add2(add2(u2.x, u4.x), add2(u6.x, u8.x)));
            u64 sy = add2(add2(yp[2 * cc + 1], u1.y),
                          add2(add2(u2.y, u4.y), add2(u6.y, u8.y)));
            *(ulonglong2*)(yg + cc * 4) = make_ulonglong2(mul2(sx, inv2), mul2(sy, inv2));
        }
    }
}

// ---------------------------------------------------------------------------
extern "C" void kernel_launch(void* const* d_in, const int* in_sizes, int n_in,
                              void* d_out, int out_size)
{
    const float* q = (const float*)d_in[0];
    const float* k = (const float*)d_in[1];
    const float* v = (const float*)d_in[2];
    float* out = (float*)d_out;
    (void)in_sizes; (void)n_in; (void)out_size;

    void *Y23, *A23, *q4, *k4, *v4, *Y45, *A45, *q6, *k6, *v6, *Y67, *A67;
    void *q8, *k8, *v8, *Y8, *A8;
    cudaGetSymbolAddress(&Y23, g_Y23);
    cudaGetSymbolAddress(&A23, g_A23);
    cudaGetSymbolAddress(&q4, g_q4);
    cudaGetSymbolAddress(&k4, g_k4);
    cudaGetSymbolAddress(&v4, g_v4);
    cudaGetSymbolAddress(&Y45, g_Y45);
    cudaGetSymbolAddress(&A45, g_A45);
    cudaGetSymbolAddress(&q6, g_q6);
    cudaGetSymbolAddress(&k6, g_k6);
    cudaGetSymbolAddress(&v6, g_v6);
    cudaGetSymbolAddress(&Y67, g_Y67);
    cudaGetSymbolAddress(&A67, g_A67);
    cudaGetSymbolAddress(&q8, g_q8);
    cudaGetSymbolAddress(&k8, g_k8);
    cudaGetSymbolAddress(&v8, g_v8);
    cudaGetSymbolAddress(&Y8, g_Y8);
    cudaGetSymbolAddress(&A8, g_A8);

    const int S23 = (64 * SD * 3 + 32 * SD * 4 + 32 + 16 * SD * 3) * (int)sizeof(float); // 100224
    const int ST  = (64 * SD * 3 + 32 * SD * 4 + 32) * (int)sizeof(float);               // 87168
    const int SF  = (64 * SD * 3 + 32 * SD * 4 + 32 + 22 * SD + 22) * (int)sizeof(float);// 93240
    cudaFuncSetAttribute(hatt_lvl23, cudaFuncAttributeMaxDynamicSharedMemorySize, S23);
    cudaFuncSetAttribute(hatt_tail, cudaFuncAttributeMaxDynamicSharedMemorySize, ST);
    cudaFuncSetAttribute(hatt_fused01, cudaFuncAttributeMaxDynamicSharedMemorySize, SF);

    // K_A: levels 2-3 from original (pool x4 in regs) + pooled lvl4/6/8 out.
    hatt_lvl23<<<dim3(32, 32), 256, S23>>>(
        q, k, v, (float*)Y23, (float*)A23,
        (float*)q4, (float*)k4, (float*)v4,
        (float*)q6, (float*)k6, (float*)v6,
        (float*)q8, (float*)k8, (float*)v8);

    // K_T: fused tail (levels 4-5, 6-7, 8) in one launch.
    hatt_tail<<<352, 256, ST>>>(
        (const float*)q4, (const float*)k4, (const float*)v4, (float*)Y45, (float*)A45,
        (const float*)q6, (const float*)k6, (const float*)v6, (float*)Y67, (float*)A67,
        (const float*)q8, (const float*)k8, (const float*)v8, (float*)Y8, (float*)A8);

    // K_F: levels 0-1 + combine + divide -> out.
    hatt_fused01<<<dim3(128, 32), 256, SF>>>(
        q, k, v, out,
        (const float*)Y23, (const float*)A23, (const float*)Y45, (const float*)A45,
        (const float*)Y67, (const float*)A67, (const float*)Y8, (const float*)A8);
}

// round 15
// speedup vs baseline: 1.1414x; 1.0281x over previous
#include <cuda_runtime.h>

// ---------------------------------------------------------------------------
// HAttention1D: b=4 h=8 n=8192 d=64, block=16, 9 levels (0..8).
// R13: exact R9 structure (best known: 162.5us) + CORRECTED wave stagger:
//      only thread 0 spins, rest park at a barrier (no issue pollution);
//      delay ~= one load phase, not one full compute phase.
//   K_A  hatt_lvl23  : orig->pool x4 in regs, attn lvl2-3, emit pooled 4/6/8.
//   K_T  hatt_tail   : ONE kernel, 352 CTAs: lvl4-5, lvl6-7, lvl8.
//   K_F  hatt_fused01: attn lvl0-1 + staged coarse + divide -> out.
// ---------------------------------------------------------------------------

#define BHN 32
#define N0  8192
#define DD  64
#define SD  68   // padded smem row stride in floats

typedef unsigned long long u64;

// ---- packed f32x2 helpers ----
__device__ __forceinline__ u64 pk2(float a, float b) {
    u64 r; asm("mov.b64 %0, {%1, %2};" : "=l"(r) : "f"(a), "f"(b)); return r;
}
__device__ __forceinline__ void up2(u64 v, float& a, float& b) {
    asm("mov.b64 {%0, %1}, %2;" : "=f"(a), "=f"(b) : "l"(v));
}
__device__ __forceinline__ u64 fma2(u64 a, u64 b, u64 c) {
    u64 r; asm("fma.rn.f32x2 %0, %1, %2, %3;" : "=l"(r) : "l"(a), "l"(b), "l"(c)); return r;
}
__device__ __forceinline__ u64 add2(u64 a, u64 b) {
    u64 r; asm("add.rn.f32x2 %0, %1, %2;" : "=l"(r) : "l"(a), "l"(b)); return r;
}
__device__ __forceinline__ u64 mul2(u64 a, u64 b) {
    u64 r; asm("mul.rn.f32x2 %0, %1, %2;" : "=l"(r) : "l"(a), "l"(b)); return r;
}

// ---- wave stagger: delay odd co-resident CTAs; ONLY thread 0 spins, the
// rest wait at the barrier (BAR-parked warps consume no issue slots). ----
__device__ __forceinline__ void stagger(int linear_bid, long long cycles) {
    if ((linear_bid / 148) & 1) {
        if (threadIdx.x == 0) {
            long long s = clock64();
            while (clock64() - s < cycles) { }
        }
        __syncthreads();
    }
}

// ---- scratch (device globals; no allocations allowed) ----
__device__ __align__(16) float g_Y23[(size_t)BHN * (N0 / 4) * DD];   // 16 MB
__device__ __align__(16) float g_A23[BHN * (N0 / 4)];
__device__ __align__(16) float g_q4[BHN * (N0 / 16) * DD];           // 4 MB ea
__device__ __align__(16) float g_k4[BHN * (N0 / 16) * DD];
__device__ __align__(16) float g_v4[BHN * (N0 / 16) * DD];
__device__ __align__(16) float g_Y45[BHN * (N0 / 16) * DD];
__device__ __align__(16) float g_A45[BHN * (N0 / 16)];
__device__ __align__(16) float g_q6[BHN * (N0 / 64) * DD];           // 1 MB ea
__device__ __align__(16) float g_k6[BHN * (N0 / 64) * DD];
__device__ __align__(16) float g_v6[BHN * (N0 / 64) * DD];
__device__ __align__(16) float g_Y67[BHN * (N0 / 64) * DD];
__device__ __align__(16) float g_A67[BHN * (N0 / 64)];
__device__ __align__(16) float g_q8[BHN * (N0 / 256) * DD];          // 256 KB ea
__device__ __align__(16) float g_k8[BHN * (N0 / 256) * DD];
__device__ __align__(16) float g_v8[BHN * (N0 / 256) * DD];
__device__ __align__(16) float g_Y8[BHN * (N0 / 256) * DD];
__device__ __align__(16) float g_A8[BHN * (N0 / 256)];

__device__ __forceinline__ float4 f4_scale(float4 a, float s) {
    return make_float4(a.x * s, a.y * s, a.z * s, a.w * s);
}
__device__ __forceinline__ float4 f4_add(float4 a, float4 b) {
    return make_float4(a.x + b.x, a.y + b.y, a.z + b.z, a.w + b.w);
}
__device__ __forceinline__ float4 f4_avg(float4 a, float4 b) {
    return make_float4((a.x + b.x) * 0.5f, (a.y + b.y) * 0.5f,
                       (a.z + b.z) * 0.5f, (a.w + b.w) * 0.5f);
}

// ---------------------------------------------------------------------------
// One warp: full 16x16 block attention. Lane (i, dg): query row i, d-half dg.
// ---------------------------------------------------------------------------
__device__ __forceinline__ float attn_block(
    const float* __restrict__ qB, const float* __restrict__ kB,
    const float* __restrict__ vB, int i, int dg, u64 yp[16])
{
    const float* qr = qB + i * SD;
    const float* kr = kB + dg * 8 * SD;
    u64 acc[8];
#pragma unroll
    for (int jj = 0; jj < 8; jj++) acc[jj] = 0ull;
#pragma unroll
    for (int c4 = 0; c4 < 16; c4++) {
        ulonglong2 qv = *(const ulonglong2*)(qr + c4 * 4);
#pragma unroll
        for (int jj = 0; jj < 8; jj++) {
            ulonglong2 kv = *(const ulonglong2*)(kr + jj * SD + c4 * 4);
            acc[jj] = fma2(qv.x, kv.x, acc[jj]);
            acc[jj] = fma2(qv.y, kv.y, acc[jj]);
        }
    }
    float s[8];
#pragma unroll
    for (int jj = 0; jj < 8; jj++) { float lo, hi; up2(acc[jj], lo, hi); s[jj] = lo + hi; }
    float m = s[0];
#pragma unroll
    for (int jj = 1; jj < 8; jj++) m = fmaxf(m, s[jj]);
    m = fmaxf(m, __shfl_xor_sync(0xffffffffu, m, 16));
    float A[8];
    float rs = 0.f;
#pragma unroll
    for (int jj = 0; jj < 8; jj++) { A[jj] = __expf(s[jj] - m); rs += A[jj]; }
    rs += __shfl_xor_sync(0xffffffffu, rs, 16);
    float Af0[8], Af1[8];
#pragma unroll
    for (int jj = 0; jj < 8; jj++) {
        float o = __shfl_xor_sync(0xffffffffu, A[jj], 16);
        Af0[jj] = dg ? o : A[jj];
        Af1[jj] = dg ? A[jj] : o;
    }
#pragma unroll
    for (int cc = 0; cc < 16; cc++) yp[cc] = 0ull;
#pragma unroll
    for (int jj = 0; jj < 8; jj++) {
        u64 a0 = pk2(Af0[jj], Af0[jj]);
        u64 a1 = pk2(Af1[jj], Af1[jj]);
        const ulonglong2* vr0 = (const ulonglong2*)(vB + jj * SD + (dg << 5));
        const ulonglong2* vr1 = (const ulonglong2*)(vB + (8 + jj) * SD + (dg << 5));
#pragma unroll
        for (int cc = 0; cc < 8; cc++) {
            ulonglong2 v0 = vr0[cc];
            ulonglong2 v1 = vr1[cc];
            yp[2 * cc]     = fma2(a0, v0.x, yp[2 * cc]);
            yp[2 * cc + 1] = fma2(a0, v0.y, yp[2 * cc + 1]);
            yp[2 * cc]     = fma2(a1, v1.x, yp[2 * cc]);
            yp[2 * cc + 1] = fma2(a1, v1.y, yp[2 * cc + 1]);
        }
    }
    return rs;
}

// ===========================================================================
// K_A: levels 2-3 from ORIGINAL inputs (pool x4 in registers during load).
// Chunk = 256 orig tokens = 64 lvl2 tokens. Warps 0-3: lvl2 blocks (flip);
// 4-5: lvl3 blocks (flip); 6: lvl6 pool-out; 7: lvl8 pool-out.
// ===========================================================================
__global__ void __launch_bounds__(256, 2)
hatt_lvl23(const float* __restrict__ Q, const float* __restrict__ K,
           const float* __restrict__ V,
           float* __restrict__ Y23, float* __restrict__ A23,
           float* __restrict__ q4, float* __restrict__ k4, float* __restrict__ v4,
           float* __restrict__ q6, float* __restrict__ k6, float* __restrict__ v6,
           float* __restrict__ q8, float* __restrict__ k8, float* __restrict__ v8)
{
    extern __shared__ float sm[];
    float* s_q0 = sm;                     // 64*SD  (lvl2)
    float* s_k0 = s_q0 + 64 * SD;
    float* s_v0 = s_k0 + 64 * SD;
    float* s_q1 = s_v0 + 64 * SD;         // 32*SD  (lvl3)
    float* s_k1 = s_q1 + 32 * SD;
    float* s_v1 = s_k1 + 32 * SD;
    float* s_y1 = s_v1 + 32 * SD;         // 32*SD
    float* s_a1 = s_y1 + 32 * SD;         // 32
    float* s_p4q = s_a1 + 32;             // 16*SD (lvl4 stage)
    float* s_p4k = s_p4q + 16 * SD;
    float* s_p4v = s_p4k + 16 * SD;

    const int tid = threadIdx.x;
    const int bh = blockIdx.y;
    const int c = blockIdx.x;             // 0..31
    const size_t baseO = ((size_t)bh * N0 + (size_t)c * 256) * DD;

    stagger(bh * 32 + c, 9000);           // ~ one load phase

    // ---- Phase 1: each thread loads 16 orig rows at one f4-col, pools ----
    {
        const int u = tid >> 4, cq = tid & 15, c4 = cq << 2;
        const float4* qf = (const float4*)(Q + baseO);
        const float4* kf = (const float4*)(K + baseO);
        const float4* vf = (const float4*)(V + baseO);
        const int i0 = (u << 8) + cq;
        float4 l2q[4], l2k[4], l2v[4];
#pragma unroll
        for (int g = 0; g < 4; g++) {
            int ib = i0 + (g << 6);
            float4 a0 = qf[ib], a1 = qf[ib + 16], a2 = qf[ib + 32], a3 = qf[ib + 48];
            l2q[g] = f4_scale(f4_avg(f4_avg(a0, a1), f4_avg(a2, a3)), 0.125f);
            float4 b0 = kf[ib], b1 = kf[ib + 16], b2 = kf[ib + 32], b3 = kf[ib + 48];
            l2k[g] = f4_avg(f4_avg(b0, b1), f4_avg(b2, b3));
            float4 d0 = vf[ib], d1 = vf[ib + 16], d2 = vf[ib + 32], d3 = vf[ib + 48];
            l2v[g] = f4_add(f4_add(d0, d1), f4_add(d2, d3));
        }
        const int r0 = (u << 2) * SD + c4;
#pragma unroll
        for (int g = 0; g < 4; g++) {
            *(float4*)(s_q0 + r0 + g * SD) = l2q[g];
            *(float4*)(s_k0 + r0 + g * SD) = l2k[g];
            *(float4*)(s_v0 + r0 + g * SD) = l2v[g];
        }
        float4 q3a = f4_avg(l2q[0], l2q[1]), q3b = f4_avg(l2q[2], l2q[3]);
        float4 k3a = f4_avg(l2k[0], l2k[1]), k3b = f4_avg(l2k[2], l2k[3]);
        float4 v3a = f4_add(l2v[0], l2v[1]), v3b = f4_add(l2v[2], l2v[3]);
        const int r1 = (u << 1) * SD + c4;
        *(float4*)(s_q1 + r1) = q3a;  *(float4*)(s_q1 + r1 + SD) = q3b;
        *(float4*)(s_k1 + r1) = k3a;  *(float4*)(s_k1 + r1 + SD) = k3b;
        *(float4*)(s_v1 + r1) = v3a;  *(float4*)(s_v1 + r1 + SD) = v3b;
        float4 q4r = f4_avg(q3a, q3b), k4r = f4_avg(k3a, k3b), v4r = f4_add(v3a, v3b);
        *(float4*)(s_p4q + u * SD + c4) = q4r;
        *(float4*)(s_p4k + u * SD + c4) = k4r;
        *(float4*)(s_p4v + u * SD + c4) = v4r;
        const size_t gi = ((size_t)(bh * 512 + c * 16 + u)) * 16 + cq;
        ((float4*)q4)[gi] = q4r; ((float4*)k4)[gi] = k4r; ((float4*)v4)[gi] = v4r;
    }
    __syncthreads();

    const int w = tid >> 5, lane = tid & 31, i = lane & 15, dg = lane >> 4;
    u64 yp[16];
    float rs = 0.f;
    if (w < 4) {
        int sb = w ^ 1;
        rs = attn_block(s_q0 + w * 16 * SD, s_k0 + sb * 16 * SD,
                        s_v0 + sb * 16 * SD, i, dg, yp);
    } else if (w < 6) {
        int qb = w - 4, sb = qb ^ 1;
        rs = attn_block(s_q1 + qb * 16 * SD, s_k1 + sb * 16 * SD,
                        s_v1 + sb * 16 * SD, i, dg, yp);
        float* yo = s_y1 + (qb * 16 + i) * SD + (dg << 5);
#pragma unroll
        for (int cc = 0; cc < 8; cc++)
            *(ulonglong2*)(yo + cc * 4) = make_ulonglong2(yp[2 * cc], yp[2 * cc + 1]);
        if (dg == 0) s_a1[qb * 16 + i] = rs;
    } else if (w == 6) {
        // lvl6 pool-out: 4 rows x 16 cols from the 16 staged lvl4 rows
#pragma unroll
        for (int it = 0; it < 2; it++) {
            int idx = (it << 5) + lane;
            int t = idx >> 4, cq = idx & 15, c4s = cq << 2;
            const float* pq = s_p4q + (t << 2) * SD + c4s;
            const float* pk = s_p4k + (t << 2) * SD + c4s;
            const float* pv = s_p4v + (t << 2) * SD + c4s;
            float4 r6q = f4_avg(f4_avg(*(const float4*)pq, *(const float4*)(pq + SD)),
                                f4_avg(*(const float4*)(pq + 2 * SD), *(const float4*)(pq + 3 * SD)));
            float4 r6k = f4_avg(f4_avg(*(const float4*)pk, *(const float4*)(pk + SD)),
                                f4_avg(*(const float4*)(pk + 2 * SD), *(const float4*)(pk + 3 * SD)));
            float4 r6v = f4_add(f4_add(*(const float4*)pv, *(const float4*)(pv + SD)),
                                f4_add(*(const float4*)(pv + 2 * SD), *(const float4*)(pv + 3 * SD)));
            const size_t gi = ((size_t)(bh * 128 + (c << 2) + t)) * 16 + cq;
            ((float4*)q6)[gi] = r6q; ((float4*)k6)[gi] = r6k; ((float4*)v6)[gi] = r6v;
        }
    } else {
        // lvl8 pool-out: 1 row per chunk; pairwise tree over 16 lvl4 rows.
        if (lane < 16) {
            int c4s = lane << 2;
            const size_t gi = ((size_t)(bh * 32 + c)) * 16 + lane;
            {
                float4 t5[8];
#pragma unroll
                for (int j = 0; j < 8; j++) {
                    const float* p = s_p4q + (2 * j) * SD + c4s;
                    t5[j] = f4_avg(*(const float4*)p, *(const float4*)(p + SD));
                }
                float4 t6a = f4_avg(t5[0], t5[1]), t6b = f4_avg(t5[2], t5[3]);
                float4 t6c = f4_avg(t5[4], t5[5]), t6d = f4_avg(t5[6], t5[7]);
                ((float4*)q8)[gi] = f4_avg(f4_avg(t6a, t6b), f4_avg(t6c, t6d));
            }
            {
                float4 t5[8];
#pragma unroll
                for (int j = 0; j < 8; j++) {
                    const float* p = s_p4k + (2 * j) * SD + c4s;
                    t5[j] = f4_avg(*(const float4*)p, *(const float4*)(p + SD));
                }
                float4 t6a = f4_avg(t5[0], t5[1]), t6b = f4_avg(t5[2], t5[3]);
                float4 t6c = f4_avg(t5[4], t5[5]), t6d = f4_avg(t5[6], t5[7]);
                ((float4*)k8)[gi] = f4_avg(f4_avg(t6a, t6b), f4_avg(t6c, t6d));
            }
            {
                float4 t5[8];
#pragma unroll
                for (int j = 0; j < 8; j++) {
                    const float* p = s_p4v + (2 * j) * SD + c4s;
                    t5[j] = f4_add(*(const float4*)p, *(const float4*)(p + SD));
                }
                float4 t6a = f4_add(t5[0], t5[1]), t6b = f4_add(t5[2], t5[3]);
                float4 t6c = f4_add(t5[4], t5[5]), t6d = f4_add(t5[6], t5[7]);
                ((float4*)v8)[gi] = f4_add(f4_add(t6a, t6b), f4_add(t6c, t6d));
            }
        }
    }
    __syncthreads();

    if (w < 4) {
        const int r = (w << 4) + i;
        const float* y1r = s_y1 + (r >> 1) * SD + (dg << 5);
        float* yg = Y23 + ((size_t)bh * 2048 + (size_t)c * 64 + r) * DD + (dg << 5);
#pragma unroll
        for (int cc = 0; cc < 8; cc++) {
            ulonglong2 u1 = *(const ulonglong2*)(y1r + cc * 4);
            *(ulonglong2*)(yg + cc * 4) =
                make_ulonglong2(add2(yp[2 * cc], u1.x), add2(yp[2 * cc + 1], u1.y));
        }
        if (dg == 0)
            A23[bh * 2048 + c * 64 + r] = rs + s_a1[r >> 1];
    }
}

// ===========================================================================
// K_T: fused tail. 352 CTAs: [0,256) lvl4-5; [256,320) lvl6-7; [320,352) lvl8.
// ===========================================================================
__global__ void __launch_bounds__(256, 2)
hatt_tail(const float* __restrict__ q4, const float* __restrict__ k4,
          const float* __restrict__ v4, float* __restrict__ Y45, float* __restrict__ A45,
          const float* __restrict__ q6, const float* __restrict__ k6,
          const float* __restrict__ v6, float* __restrict__ Y67, float* __restrict__ A67,
          const float* __restrict__ q8, const float* __restrict__ k8,
          const float* __restrict__ v8, float* __restrict__ Y8, float* __restrict__ A8)
{
    extern __shared__ float sm[];
    float* s_q0 = sm;
    float* s_k0 = s_q0 + 64 * SD;
    float* s_v0 = s_k0 + 64 * SD;
    float* s_q1 = s_v0 + 64 * SD;
    float* s_k1 = s_q1 + 32 * SD;
    float* s_v1 = s_k1 + 32 * SD;
    float* s_y1 = s_v1 + 32 * SD;
    float* s_a1 = s_y1 + 32 * SD;

    const int tid = threadIdx.x;
    const int bid = blockIdx.x;
    const int w = tid >> 5, lane = tid & 31, i = lane & 15, dg = lane >> 4;

    if (bid < 320) {
        const float *Q, *K, *V;
        float *Yd, *Ad;
        int ntok, c, bh;
        if (bid < 256) {
            bh = bid >> 3; c = bid & 7; ntok = 512;
            Q = q4; K = k4; V = v4; Yd = Y45; Ad = A45;
        } else {
            int b2 = bid - 256;
            bh = b2 >> 1; c = b2 & 1; ntok = 128;
            Q = q6; K = k6; V = v6; Yd = Y67; Ad = A67;
        }
        const size_t base = ((size_t)bh * ntok + (size_t)c * 64) * DD;

        {
            const int u = tid >> 4, cq = tid & 15, c4 = cq << 2;
            const float4* qf = (const float4*)(Q + base);
            const float4* kf = (const float4*)(K + base);
            const float4* vf = (const float4*)(V + base);
            const int i0 = (u << 6) + cq;
            float4 a0 = qf[i0], a1 = qf[i0 + 16], a2 = qf[i0 + 32], a3 = qf[i0 + 48];
            float4 b0 = kf[i0], b1 = kf[i0 + 16], b2 = kf[i0 + 32], b3 = kf[i0 + 48];
            float4 d0 = vf[i0], d1 = vf[i0 + 16], d2 = vf[i0 + 32], d3 = vf[i0 + 48];
            const int r0 = (u << 2) * SD + c4;
            *(float4*)(s_q0 + r0) = a0;           *(float4*)(s_q0 + r0 + SD) = a1;
            *(float4*)(s_q0 + r0 + 2 * SD) = a2;  *(float4*)(s_q0 + r0 + 3 * SD) = a3;
            *(float4*)(s_k0 + r0) = b0;           *(float4*)(s_k0 + r0 + SD) = b1;
            *(float4*)(s_k0 + r0 + 2 * SD) = b2;  *(float4*)(s_k0 + r0 + 3 * SD) = b3;
            *(float4*)(s_v0 + r0) = d0;           *(float4*)(s_v0 + r0 + SD) = d1;
            *(float4*)(s_v0 + r0 + 2 * SD) = d2;  *(float4*)(s_v0 + r0 + 3 * SD) = d3;
            const int r1 = (u << 1) * SD + c4;
            *(float4*)(s_q1 + r1) = f4_avg(a0, a1);  *(float4*)(s_q1 + r1 + SD) = f4_avg(a2, a3);
            *(float4*)(s_k1 + r1) = f4_avg(b0, b1);  *(float4*)(s_k1 + r1 + SD) = f4_avg(b2, b3);
            *(float4*)(s_v1 + r1) = f4_add(d0, d1);  *(float4*)(s_v1 + r1 + SD) = f4_add(d2, d3);
        }
        __syncthreads();

        u64 yp[16];
        float rs = 0.f;
        if (w < 4) {
            int sb = w ^ 1;
            rs = attn_block(s_q0 + w * 16 * SD, s_k0 + sb * 16 * SD,
                            s_v0 + sb * 16 * SD, i, dg, yp);
        } else if (w < 6) {
            int qb = w - 4, sb = qb ^ 1;
            rs = attn_block(s_q1 + qb * 16 * SD, s_k1 + sb * 16 * SD,
                            s_v1 + sb * 16 * SD, i, dg, yp);
            float* yo = s_y1 + (qb * 16 + i) * SD + (dg << 5);
#pragma unroll
            for (int cc = 0; cc < 8; cc++)
                *(ulonglong2*)(yo + cc * 4) = make_ulonglong2(yp[2 * cc], yp[2 * cc + 1]);
            if (dg == 0) s_a1[qb * 16 + i] = rs;
        }
        __syncthreads();

        if (w < 4) {
            const int r = (w << 4) + i;
            const float* y1r = s_y1 + (r >> 1) * SD + (dg << 5);
            float* yg = Yd + base + (size_t)r * DD + (dg << 5);
#pragma unroll
            for (int cc = 0; cc < 8; cc++) {
                ulonglong2 u1 = *(const ulonglong2*)(y1r + cc * 4);
                *(ulonglong2*)(yg + cc * 4) =
                    make_ulonglong2(add2(yp[2 * cc], u1.x), add2(yp[2 * cc + 1], u1.y));
            }
            if (dg == 0)
                Ad[bh * ntok + c * 64 + r] = rs + s_a1[r >> 1];
        }
    } else {
        const int bh = bid - 320;
        const size_t base = (size_t)bh * 32 * DD;
        const float4* qf = (const float4*)(q8 + base);
        const float4* kf = (const float4*)(k8 + base);
        const float4* vf = (const float4*)(v8 + base);
        for (int idx = tid; idx < 512; idx += 256) {
            int row = idx >> 4, c4 = (idx & 15) << 2;
            *(float4*)(s_q0 + row * SD + c4) = qf[idx];
            *(float4*)(s_k0 + row * SD + c4) = kf[idx];
            *(float4*)(s_v0 + row * SD + c4) = vf[idx];
        }
        __syncthreads();
        if (w < 2) {
            u64 yp[16];
            float rs = attn_block(s_q0 + w * 16 * SD, s_k0 + (w ^ 1) * 16 * SD,
                                  s_v0 + (w ^ 1) * 16 * SD, i, dg, yp);
            float* yg = Y8 + base + (size_t)((w << 4) + i) * DD + (dg << 5);
#pragma unroll
            for (int cc = 0; cc < 8; cc++)
                *(ulonglong2*)(yg + cc * 4) = make_ulonglong2(yp[2 * cc], yp[2 * cc + 1]);
            if (dg == 0) A8[bh * 32 + (w << 4) + i] = rs;
        }
    }
}

// ===========================================================================
// K_F: levels 0-1 + final combine. Warps 6/7 stage coarse Y/A into smem
// during the attention phase; Phase C sums all levels, divides, writes out.
// ===========================================================================
__global__ void __launch_bounds__(256, 2)
hatt_fused01(const float* __restrict__ Q, const float* __restrict__ K,
             const float* __restrict__ V, float* __restrict__ out,
             const float* __restrict__ Y23, const float* __restrict__ A23,
             const float* __restrict__ Y45, const float* __restrict__ A45,
             const float* __restrict__ Y67, const float* __restrict__ A67,
             const float* __restrict__ Y8, const float* __restrict__ A8)
{
    extern __shared__ float sm[];
    float* s_q0 = sm;                     // 64*SD
    float* s_k0 = s_q0 + 64 * SD;
    float* s_v0 = s_k0 + 64 * SD;
    float* s_q1 = s_v0 + 64 * SD;         // 32*SD
    float* s_k1 = s_q1 + 32 * SD;
    float* s_v1 = s_k1 + 32 * SD;
    float* s_y1 = s_v1 + 32 * SD;         // 32*SD
    float* s_a1 = s_y1 + 32 * SD;         // 32
    float* s_c = s_a1 + 32;               // 22*SD coarse Y stage
    float* s_ca = s_c + 22 * SD;          // 22 coarse A stage

    const int tid = threadIdx.x;
    const int bh = blockIdx.y;
    const int c = blockIdx.x;             // 0..127
    const size_t base = ((size_t)bh * N0 + (size_t)c * 64) * DD;

    stagger(bh * 128 + c, 4500);          // ~ one load phase

    // ---- Phase 1: load 64 orig rows (scaled q) + pool lvl1 locally ----
    {
        const int u = tid >> 4, cq = tid & 15, c4 = cq << 2;
        const float4* qf = (const float4*)(Q + base);
        const float4* kf = (const float4*)(K + base);
        const float4* vf = (const float4*)(V + base);
        const int i0 = (u << 6) + cq;
        float4 a0 = f4_scale(qf[i0], 0.125f), a1 = f4_scale(qf[i0 + 16], 0.125f);
        float4 a2 = f4_scale(qf[i0 + 32], 0.125f), a3 = f4_scale(qf[i0 + 48], 0.125f);
        float4 b0 = kf[i0], b1 = kf[i0 + 16], b2 = kf[i0 + 32], b3 = kf[i0 + 48];
        float4 d0 = vf[i0], d1 = vf[i0 + 16], d2 = vf[i0 + 32], d3 = vf[i0 + 48];
        const int r0 = (u << 2) * SD + c4;
        *(float4*)(s_q0 + r0) = a0;           *(float4*)(s_q0 + r0 + SD) = a1;
        *(float4*)(s_q0 + r0 + 2 * SD) = a2;  *(float4*)(s_q0 + r0 + 3 * SD) = a3;
        *(float4*)(s_k0 + r0) = b0;           *(float4*)(s_k0 + r0 + SD) = b1;
        *(float4*)(s_k0 + r0 + 2 * SD) = b2;  *(float4*)(s_k0 + r0 + 3 * SD) = b3;
        *(float4*)(s_v0 + r0) = d0;           *(float4*)(s_v0 + r0 + SD) = d1;
        *(float4*)(s_v0 + r0 + 2 * SD) = d2;  *(float4*)(s_v0 + r0 + 3 * SD) = d3;
        const int r1 = (u << 1) * SD + c4;
        *(float4*)(s_q1 + r1) = f4_avg(a0, a1);  *(float4*)(s_q1 + r1 + SD) = f4_avg(a2, a3);
        *(float4*)(s_k1 + r1) = f4_avg(b0, b1);  *(float4*)(s_k1 + r1 + SD) = f4_avg(b2, b3);
        *(float4*)(s_v1 + r1) = f4_add(d0, d1);  *(float4*)(s_v1 + r1 + SD) = f4_add(d2, d3);
    }
    __syncthreads();

    const int w = tid >> 5, lane = tid & 31, i = lane & 15, dg = lane >> 4;
    u64 yp[16];
    float rs = 0.f;
    if (w < 4) {
        // level 0: SELF-attention (no flip)
        rs = attn_block(s_q0 + w * 16 * SD, s_k0 + w * 16 * SD,
                        s_v0 + w * 16 * SD, i, dg, yp);
    } else if (w < 6) {
        int qb = w - 4, sb = qb ^ 1;
        rs = attn_block(s_q1 + qb * 16 * SD, s_k1 + sb * 16 * SD,
                        s_v1 + sb * 16 * SD, i, dg, yp);
        float* yo = s_y1 + (qb * 16 + i) * SD + (dg << 5);
#pragma unroll
        for (int cc = 0; cc < 8; cc++)
            *(ulonglong2*)(yo + cc * 4) = make_ulonglong2(yp[2 * cc], yp[2 * cc + 1]);
        if (dg == 0) s_a1[qb * 16 + i] = rs;
    } else if (w == 6) {
        // stage Y23: 16 rows (rows 0-15 of s_c)
        const float4* y23f = (const float4*)Y23;
#pragma unroll
        for (int it = 0; it < 8; it++) {
            int idx = (it << 5) + lane;
            int t = idx >> 4, cq = idx & 15;
            *(float4*)(s_c + t * SD + (cq << 2)) =
                y23f[((size_t)bh * 2048 + (size_t)c * 16 + t) * 16 + cq];
        }
    } else {
        // w==7: stage Y45 (rows 16-19), Y67 (20), Y8 (21), all coarse A's
        const float4* y45f = (const float4*)Y45;
#pragma unroll
        for (int it = 0; it < 2; it++) {
            int idx = (it << 5) + lane;
            int t = idx >> 4, cq = idx & 15;
            *(float4*)(s_c + (16 + t) * SD + (cq << 2)) =
                y45f[((size_t)bh * 512 + (size_t)c * 4 + t) * 16 + cq];
        }
        if (lane < 16) {
            *(float4*)(s_c + 20 * SD + (lane << 2)) =
                ((const float4*)Y67)[((size_t)bh * 128 + c) * 16 + lane];
            *(float4*)(s_c + 21 * SD + (lane << 2)) =
                ((const float4*)Y8)[((size_t)bh * 32 + (c >> 2)) * 16 + lane];
            s_ca[lane] = A23[bh * 2048 + c * 16 + lane];
        }
        if (lane < 4) s_ca[16 + lane] = A45[bh * 512 + c * 4 + lane];
        if (lane == 0) {
            s_ca[20] = A67[bh * 128 + c];
            s_ca[21] = A8[bh * 32 + (c >> 2)];
        }
    }
    __syncthreads();

    // ---- Phase C (w 0-3): sum all levels, divide, write out ----
    if (w < 4) {
        const int r = (w << 4) + i;
        float a = rs + s_a1[r >> 1] + s_ca[r >> 2] + s_ca[16 + (r >> 4)]
                + s_ca[20] + s_ca[21] + 1e-8f;
        float inv = 1.0f / a;
        u64 inv2 = pk2(inv, inv);
        const float* y1r = s_y1 + (r >> 1) * SD + (dg << 5);
        const float* c2p = s_c + (r >> 2) * SD + (dg << 5);
        const float* c4p = s_c + (16 + (r >> 4)) * SD + (dg << 5);
        const float* c6p = s_c + 20 * SD + (dg << 5);
        const float* c8p = s_c + 21 * SD + (dg << 5);
        float* yg = out + base + (size_t)r * DD + (dg << 5);
#pragma unroll
        for (int cc = 0; cc < 8; cc++) {
            ulonglong2 u1 = *(const ulonglong2*)(y1r + cc * 4);
            ulonglong2 u2 = *(const ulonglong2*)(c2p + cc * 4);
            ulonglong2 u4 = *(const ulonglong2*)(c4p + cc * 4);
            ulonglong2 u6 = *(const ulonglong2*)(c6p + cc * 4);
            ulonglong2 u8 = *(const ulonglong2*)(c8p + cc * 4);
            u64 sx = add2(add2(yp[2 * cc], u1.x),
                          add2(add2(u2.x, u4.x), add2(u6.x, u8.x)));
            u64 sy = add2(add2(yp[2 * cc + 1], u1.y),
                          add2(add2(u2.y, u4.y), add2(u6.y, u8.y)));
            *(ulonglong2*)(yg + cc * 4) = make_ulonglong2(mul2(sx, inv2), mul2(sy, inv2));
        }
    }
}

// ---------------------------------------------------------------------------
extern "C" void kernel_launch(void* const* d_in, const int* in_sizes, int n_in,
                              void* d_out, int out_size)
{
    const float* q = (const float*)d_in[0];
    const float* k = (const float*)d_in[1];
    const float* v = (const float*)d_in[2];
    float* out = (float*)d_out;
    (void)in_sizes; (void)n_in; (void)out_size;

    void *Y23, *A23, *q4, *k4, *v4, *Y45, *A45, *q6, *k6, *v6, *Y67, *A67;
    void *q8, *k8, *v8, *Y8, *A8;
    cudaGetSymbolAddress(&Y23, g_Y23);
    cudaGetSymbolAddress(&A23, g_A23);
    cudaGetSymbolAddress(&q4, g_q4);
    cudaGetSymbolAddress(&k4, g_k4);
    cudaGetSymbolAddress(&v4, g_v4);
    cudaGetSymbolAddress(&Y45, g_Y45);
    cudaGetSymbolAddress(&A45, g_A45);
    cudaGetSymbolAddress(&q6, g_q6);
    cudaGetSymbolAddress(&k6, g_k6);
    cudaGetSymbolAddress(&v6, g_v6);
    cudaGetSymbolAddress(&Y67, g_Y67);
    cudaGetSymbolAddress(&A67, g_A67);
    cudaGetSymbolAddress(&q8, g_q8);
    cudaGetSymbolAddress(&k8, g_k8);
    cudaGetSymbolAddress(&v8, g_v8);
    cudaGetSymbolAddress(&Y8, g_Y8);
    cudaGetSymbolAddress(&A8, g_A8);

    const int S23 = (64 * SD * 3 + 32 * SD * 4 + 32 + 16 * SD * 3) * (int)sizeof(float); // 100224
    const int ST  = (64 * SD * 3 + 32 * SD * 4 + 32) * (int)sizeof(float);               // 87168
    const int SF  = (64 * SD * 3 + 32 * SD * 4 + 32 + 22 * SD + 22) * (int)sizeof(float);// 93240
    cudaFuncSetAttribute(hatt_lvl23, cudaFuncAttributeMaxDynamicSharedMemorySize, S23);
    cudaFuncSetAttribute(hatt_tail, cudaFuncAttributeMaxDynamicSharedMemorySize, ST);
    cudaFuncSetAttribute(hatt_fused01, cudaFuncAttributeMaxDynamicSharedMemorySize, SF);

    // K_A: levels 2-3 from original (pool x4 in regs) + pooled lvl4/6/8 out.
    hatt_lvl23<<<dim3(32, 32), 256, S23>>>(
        q, k, v, (float*)Y23, (float*)A23,
        (float*)q4, (float*)k4, (float*)v4,
        (float*)q6, (float*)k6, (float*)v6,
        (float*)q8, (float*)k8, (float*)v8);

    // K_T: fused tail (levels 4-5, 6-7, 8) in one launch.
    hatt_tail<<<352, 256, ST>>>(
        (const float*)q4, (const float*)k4, (const float*)v4, (float*)Y45, (float*)A45,
        (const float*)q6, (const float*)k6, (const float*)v6, (float*)Y67, (float*)A67,
        (const float*)q8, (const float*)k8, (const float*)v8, (float*)Y8, (float*)A8);

    // K_F: levels 0-1 + combine + divide -> out.
    hatt_fused01<<<dim3(128, 32), 256, SF>>>(
        q, k, v, out,
        (const float*)Y23, (const float*)A23, (const float*)Y45, (const float*)A45,
        (const float*)Y67, (const float*)A67, (const float*)Y8, (const float*)A8);
}

// round 17
// speedup vs baseline: 1.2387x; 1.0852x over previous
#include <cuda_runtime.h>

// ---------------------------------------------------------------------------
// HAttention1D: b=4 h=8 n=8192 d=64, block=16, 9 levels (0..8).
// R15: exact R9 structure (best known: 162.5us), stagger removed, and
//      lvl23 phase-1 loads front-batched per array (MLP 4 -> 16) to hide
//      DRAM latency in the load phase.
//   K_A  hatt_lvl23  : orig->pool x4 in regs, attn lvl2-3, emit pooled 4/6/8.
//   K_T  hatt_tail   : ONE kernel, 352 CTAs: lvl4-5, lvl6-7, lvl8.
//   K_F  hatt_fused01: attn lvl0-1 + staged coarse + divide -> out.
// ---------------------------------------------------------------------------

#define BHN 32
#define N0  8192
#define DD  64
#define SD  68   // padded smem row stride in floats

typedef unsigned long long u64;

// ---- packed f32x2 helpers ----
__device__ __forceinline__ u64 pk2(float a, float b) {
    u64 r; asm("mov.b64 %0, {%1, %2};" : "=l"(r) : "f"(a), "f"(b)); return r;
}
__device__ __forceinline__ void up2(u64 v, float& a, float& b) {
    asm("mov.b64 {%0, %1}, %2;" : "=f"(a), "=f"(b) : "l"(v));
}
__device__ __forceinline__ u64 fma2(u64 a, u64 b, u64 c) {
    u64 r; asm("fma.rn.f32x2 %0, %1, %2, %3;" : "=l"(r) : "l"(a), "l"(b), "l"(c)); return r;
}
__device__ __forceinline__ u64 add2(u64 a, u64 b) {
    u64 r; asm("add.rn.f32x2 %0, %1, %2;" : "=l"(r) : "l"(a), "l"(b)); return r;
}
__device__ __forceinline__ u64 mul2(u64 a, u64 b) {
    u64 r; asm("mul.rn.f32x2 %0, %1, %2;" : "=l"(r) : "l"(a), "l"(b)); return r;
}

// ---- scratch (device globals; no allocations allowed) ----
__device__ __align__(16) float g_Y23[(size_t)BHN * (N0 / 4) * DD];   // 16 MB
__device__ __align__(16) float g_A23[BHN * (N0 / 4)];
__device__ __align__(16) float g_q4[BHN * (N0 / 16) * DD];           // 4 MB ea
__device__ __align__(16) float g_k4[BHN * (N0 / 16) * DD];
__device__ __align__(16) float g_v4[BHN * (N0 / 16) * DD];
__device__ __align__(16) float g_Y45[BHN * (N0 / 16) * DD];
__device__ __align__(16) float g_A45[BHN * (N0 / 16)];
__device__ __align__(16) float g_q6[BHN * (N0 / 64) * DD];           // 1 MB ea
__device__ __align__(16) float g_k6[BHN * (N0 / 64) * DD];
__device__ __align__(16) float g_v6[BHN * (N0 / 64) * DD];
__device__ __align__(16) float g_Y67[BHN * (N0 / 64) * DD];
__device__ __align__(16) float g_A67[BHN * (N0 / 64)];
__device__ __align__(16) float g_q8[BHN * (N0 / 256) * DD];          // 256 KB ea
__device__ __align__(16) float g_k8[BHN * (N0 / 256) * DD];
__device__ __align__(16) float g_v8[BHN * (N0 / 256) * DD];
__device__ __align__(16) float g_Y8[BHN * (N0 / 256) * DD];
__device__ __align__(16) float g_A8[BHN * (N0 / 256)];

__device__ __forceinline__ float4 f4_scale(float4 a, float s) {
    return make_float4(a.x * s, a.y * s, a.z * s, a.w * s);
}
__device__ __forceinline__ float4 f4_add(float4 a, float4 b) {
    return make_float4(a.x + b.x, a.y + b.y, a.z + b.z, a.w + b.w);
}
__device__ __forceinline__ float4 f4_avg(float4 a, float4 b) {
    return make_float4((a.x + b.x) * 0.5f, (a.y + b.y) * 0.5f,
                       (a.z + b.z) * 0.5f, (a.w + b.w) * 0.5f);
}

// ---------------------------------------------------------------------------
// One warp: full 16x16 block attention. Lane (i, dg): query row i, d-half dg.
// ---------------------------------------------------------------------------
__device__ __forceinline__ float attn_block(
    const float* __restrict__ qB, const float* __restrict__ kB,
    const float* __restrict__ vB, int i, int dg, u64 yp[16])
{
    const float* qr = qB + i * SD;
    const float* kr = kB + dg * 8 * SD;
    u64 acc[8];
#pragma unroll
    for (int jj = 0; jj < 8; jj++) acc[jj] = 0ull;
#pragma unroll
    for (int c4 = 0; c4 < 16; c4++) {
        ulonglong2 qv = *(const ulonglong2*)(qr + c4 * 4);
#pragma unroll
        for (int jj = 0; jj < 8; jj++) {
            ulonglong2 kv = *(const ulonglong2*)(kr + jj * SD + c4 * 4);
            acc[jj] = fma2(qv.x, kv.x, acc[jj]);
            acc[jj] = fma2(qv.y, kv.y, acc[jj]);
        }
    }
    float s[8];
#pragma unroll
    for (int jj = 0; jj < 8; jj++) { float lo, hi; up2(acc[jj], lo, hi); s[jj] = lo + hi; }
    float m = s[0];
#pragma unroll
    for (int jj = 1; jj < 8; jj++) m = fmaxf(m, s[jj]);
    m = fmaxf(m, __shfl_xor_sync(0xffffffffu, m, 16));
    float A[8];
    float rs = 0.f;
#pragma unroll
    for (int jj = 0; jj < 8; jj++) { A[jj] = __expf(s[jj] - m); rs += A[jj]; }
    rs += __shfl_xor_sync(0xffffffffu, rs, 16);
    float Af0[8], Af1[8];
#pragma unroll
    for (int jj = 0; jj < 8; jj++) {
        float o = __shfl_xor_sync(0xffffffffu, A[jj], 16);
        Af0[jj] = dg ? o : A[jj];
        Af1[jj] = dg ? A[jj] : o;
    }
#pragma unroll
    for (int cc = 0; cc < 16; cc++) yp[cc] = 0ull;
#pragma unroll
    for (int jj = 0; jj < 8; jj++) {
        u64 a0 = pk2(Af0[jj], Af0[jj]);
        u64 a1 = pk2(Af1[jj], Af1[jj]);
        const ulonglong2* vr0 = (const ulonglong2*)(vB + jj * SD + (dg << 5));
        const ulonglong2* vr1 = (const ulonglong2*)(vB + (8 + jj) * SD + (dg << 5));
#pragma unroll
        for (int cc = 0; cc < 8; cc++) {
            ulonglong2 v0 = vr0[cc];
            ulonglong2 v1 = vr1[cc];
            yp[2 * cc]     = fma2(a0, v0.x, yp[2 * cc]);
            yp[2 * cc + 1] = fma2(a0, v0.y, yp[2 * cc + 1]);
            yp[2 * cc]     = fma2(a1, v1.x, yp[2 * cc]);
            yp[2 * cc + 1] = fma2(a1, v1.y, yp[2 * cc + 1]);
        }
    }
    return rs;
}

// ---------------------------------------------------------------------------
// Load 16 float4s (front-batched LDGs), pool x4/x2 tree, write lvl2 rows +
// lvl3 rows + lvl4 row to smem. AVG: mean-pool (q,k); else sum-pool (v).
// ---------------------------------------------------------------------------
template <bool AVG>
__device__ __forceinline__ void pool16(
    const float4* __restrict__ gf, int i0, float qs,
    float* __restrict__ sL2, float* __restrict__ sL3, float* __restrict__ sP4,
    float4* __restrict__ gOut4, size_t gi,
    int r0, int r1, int r4)
{
    float4 t[16];
#pragma unroll
    for (int g = 0; g < 4; g++)
#pragma unroll
        for (int r = 0; r < 4; r++)
            t[g * 4 + r] = gf[i0 + (g << 6) + (r << 4)];   // 16 independent LDGs

    float4 l2[4];
#pragma unroll
    for (int g = 0; g < 4; g++) {
        if (AVG)
            l2[g] = f4_scale(f4_avg(f4_avg(t[g * 4], t[g * 4 + 1]),
                                    f4_avg(t[g * 4 + 2], t[g * 4 + 3])), qs);
        else
            l2[g] = f4_add(f4_add(t[g * 4], t[g * 4 + 1]),
                           f4_add(t[g * 4 + 2], t[g * 4 + 3]));
    }
#pragma unroll
    for (int g = 0; g < 4; g++)
        *(float4*)(sL2 + r0 + g * SD) = l2[g];

    float4 l3a = AVG ? f4_avg(l2[0], l2[1]) : f4_add(l2[0], l2[1]);
    float4 l3b = AVG ? f4_avg(l2[2], l2[3]) : f4_add(l2[2], l2[3]);
    *(float4*)(sL3 + r1) = l3a;
    *(float4*)(sL3 + r1 + SD) = l3b;

    float4 l4 = AVG ? f4_avg(l3a, l3b) : f4_add(l3a, l3b);
    *(float4*)(sP4 + r4) = l4;
    gOut4[gi] = l4;
}

// ===========================================================================
// K_A: levels 2-3 from ORIGINAL inputs (pool x4 in registers during load).
// Chunk = 256 orig tokens = 64 lvl2 tokens. Warps 0-3: lvl2 blocks (flip);
// 4-5: lvl3 blocks (flip); 6: lvl6 pool-out; 7: lvl8 pool-out.
// ===========================================================================
__global__ void __launch_bounds__(256, 2)
hatt_lvl23(const float* __restrict__ Q, const float* __restrict__ K,
           const float* __restrict__ V,
           float* __restrict__ Y23, float* __restrict__ A23,
           float* __restrict__ q4, float* __restrict__ k4, float* __restrict__ v4,
           float* __restrict__ q6, float* __restrict__ k6, float* __restrict__ v6,
           float* __restrict__ q8, float* __restrict__ k8, float* __restrict__ v8)
{
    extern __shared__ float sm[];
    float* s_q0 = sm;                     // 64*SD  (lvl2)
    float* s_k0 = s_q0 + 64 * SD;
    float* s_v0 = s_k0 + 64 * SD;
    float* s_q1 = s_v0 + 64 * SD;         // 32*SD  (lvl3)
    float* s_k1 = s_q1 + 32 * SD;
    float* s_v1 = s_k1 + 32 * SD;
    float* s_y1 = s_v1 + 32 * SD;         // 32*SD
    float* s_a1 = s_y1 + 32 * SD;         // 32
    float* s_p4q = s_a1 + 32;             // 16*SD (lvl4 stage)
    float* s_p4k = s_p4q + 16 * SD;
    float* s_p4v = s_p4k + 16 * SD;

    const int tid = threadIdx.x;
    const int bh = blockIdx.y;
    const int c = blockIdx.x;             // 0..31
    const size_t baseO = ((size_t)bh * N0 + (size_t)c * 256) * DD;

    // ---- Phase 1: each thread covers 16 orig rows at one f4-col.
    //      Per-array front-batched loads (MLP=16) + register pooling tree.
    {
        const int u = tid >> 4, cq = tid & 15, c4 = cq << 2;
        const int i0 = (u << 8) + cq;
        const int r0 = (u << 2) * SD + c4;
        const int r1 = (u << 1) * SD + c4;
        const int r4 = u * SD + c4;
        const size_t gi = ((size_t)(bh * 512 + c * 16 + u)) * 16 + cq;
        pool16<true>((const float4*)(Q + baseO), i0, 0.125f,
                     s_q0, s_q1, s_p4q, (float4*)q4, gi, r0, r1, r4);
        pool16<true>((const float4*)(K + baseO), i0, 1.0f,
                     s_k0, s_k1, s_p4k, (float4*)k4, gi, r0, r1, r4);
        pool16<false>((const float4*)(V + baseO), i0, 1.0f,
                      s_v0, s_v1, s_p4v, (float4*)v4, gi, r0, r1, r4);
    }
    __syncthreads();

    const int w = tid >> 5, lane = tid & 31, i = lane & 15, dg = lane >> 4;
    u64 yp[16];
    float rs = 0.f;
    if (w < 4) {
        int sb = w ^ 1;
        rs = attn_block(s_q0 + w * 16 * SD, s_k0 + sb * 16 * SD,
                        s_v0 + sb * 16 * SD, i, dg, yp);
    } else if (w < 6) {
        int qb = w - 4, sb = qb ^ 1;
        rs = attn_block(s_q1 + qb * 16 * SD, s_k1 + sb * 16 * SD,
                        s_v1 + sb * 16 * SD, i, dg, yp);
        float* yo = s_y1 + (qb * 16 + i) * SD + (dg << 5);
#pragma unroll
        for (int cc = 0; cc < 8; cc++)
            *(ulonglong2*)(yo + cc * 4) = make_ulonglong2(yp[2 * cc], yp[2 * cc + 1]);
        if (dg == 0) s_a1[qb * 16 + i] = rs;
    } else if (w == 6) {
        // lvl6 pool-out: 4 rows x 16 cols from the 16 staged lvl4 rows
#pragma unroll
        for (int it = 0; it < 2; it++) {
            int idx = (it << 5) + lane;
            int t = idx >> 4, cq = idx & 15, c4s = cq << 2;
            const float* pq = s_p4q + (t << 2) * SD + c4s;
            const float* pk = s_p4k + (t << 2) * SD + c4s;
            const float* pv = s_p4v + (t << 2) * SD + c4s;
            float4 r6q = f4_avg(f4_avg(*(const float4*)pq, *(const float4*)(pq + SD)),
                                f4_avg(*(const float4*)(pq + 2 * SD), *(const float4*)(pq + 3 * SD)));
            float4 r6k = f4_avg(f4_avg(*(const float4*)pk, *(const float4*)(pk + SD)),
                                f4_avg(*(const float4*)(pk + 2 * SD), *(const float4*)(pk + 3 * SD)));
            float4 r6v = f4_add(f4_add(*(const float4*)pv, *(const float4*)(pv + SD)),
                                f4_add(*(const float4*)(pv + 2 * SD), *(const float4*)(pv + 3 * SD)));
            const size_t gi = ((size_t)(bh * 128 + (c << 2) + t)) * 16 + cq;
            ((float4*)q6)[gi] = r6q; ((float4*)k6)[gi] = r6k; ((float4*)v6)[gi] = r6v;
        }
    } else {
        // lvl8 pool-out: 1 row per chunk; pairwise tree over 16 lvl4 rows.
        if (lane < 16) {
            int c4s = lane << 2;
            const size_t gi = ((size_t)(bh * 32 + c)) * 16 + lane;
            {
                float4 t5[8];
#pragma unroll
                for (int j = 0; j < 8; j++) {
                    const float* p = s_p4q + (2 * j) * SD + c4s;
                    t5[j] = f4_avg(*(const float4*)p, *(const float4*)(p + SD));
                }
                float4 t6a = f4_avg(t5[0], t5[1]), t6b = f4_avg(t5[2], t5[3]);
                float4 t6c = f4_avg(t5[4], t5[5]), t6d = f4_avg(t5[6], t5[7]);
                ((float4*)q8)[gi] = f4_avg(f4_avg(t6a, t6b), f4_avg(t6c, t6d));
            }
            {
                float4 t5[8];
#pragma unroll
                for (int j = 0; j < 8; j++) {
                    const float* p = s_p4k + (2 * j) * SD + c4s;
                    t5[j] = f4_avg(*(const float4*)p, *(const float4*)(p + SD));
                }
                float4 t6a = f4_avg(t5[0], t5[1]), t6b = f4_avg(t5[2], t5[3]);
                float4 t6c = f4_avg(t5[4], t5[5]), t6d = f4_avg(t5[6], t5[7]);
                ((float4*)k8)[gi] = f4_avg(f4_avg(t6a, t6b), f4_avg(t6c, t6d));
            }
            {
                float4 t5[8];
#pragma unroll
                for (int j = 0; j < 8; j++) {
                    const float* p = s_p4v + (2 * j) * SD + c4s;
                    t5[j] = f4_add(*(const float4*)p, *(const float4*)(p + SD));
                }
                float4 t6a = f4_add(t5[0], t5[1]), t6b = f4_add(t5[2], t5[3]);
                float4 t6c = f4_add(t5[4], t5[5]), t6d = f4_add(t5[6], t5[7]);
                ((float4*)v8)[gi] = f4_add(f4_add(t6a, t6b), f4_add(t6c, t6d));
            }
        }
    }
    __syncthreads();

    if (w < 4) {
        const int r = (w << 4) + i;
        const float* y1r = s_y1 + (r >> 1) * SD + (dg << 5);
        float* yg = Y23 + ((size_t)bh * 2048 + (size_t)c * 64 + r) * DD + (dg << 5);
#pragma unroll
        for (int cc = 0; cc < 8; cc++) {
            ulonglong2 u1 = *(const ulonglong2*)(y1r + cc * 4);
            *(ulonglong2*)(yg + cc * 4) =
                make_ulonglong2(add2(yp[2 * cc], u1.x), add2(yp[2 * cc + 1], u1.y));
        }
        if (dg == 0)
            A23[bh * 2048 + c * 64 + r] = rs + s_a1[r >> 1];
    }
}

// ===========================================================================
// K_T: fused tail. 352 CTAs: [0,256) lvl4-5; [256,320) lvl6-7; [320,352) lvl8.
// ===========================================================================
__global__ void __launch_bounds__(256, 2)
hatt_tail(const float* __restrict__ q4, const float* __restrict__ k4,
          const float* __restrict__ v4, float* __restrict__ Y45, float* __restrict__ A45,
          const float* __restrict__ q6, const float* __restrict__ k6,
          const float* __restrict__ v6, float* __restrict__ Y67, float* __restrict__ A67,
          const float* __restrict__ q8, const float* __restrict__ k8,
          const float* __restrict__ v8, float* __restrict__ Y8, float* __restrict__ A8)
{
    extern __shared__ float sm[];
    float* s_q0 = sm;
    float* s_k0 = s_q0 + 64 * SD;
    float* s_v0 = s_k0 + 64 * SD;
    float* s_q1 = s_v0 + 64 * SD;
    float* s_k1 = s_q1 + 32 * SD;
    float* s_v1 = s_k1 + 32 * SD;
    float* s_y1 = s_v1 + 32 * SD;
    float* s_a1 = s_y1 + 32 * SD;

    const int tid = threadIdx.x;
    const int bid = blockIdx.x;
    const int w = tid >> 5, lane = tid & 31, i = lane & 15, dg = lane >> 4;

    if (bid < 320) {
        const float *Q, *K, *V;
        float *Yd, *Ad;
        int ntok, c, bh;
        if (bid < 256) {
            bh = bid >> 3; c = bid & 7; ntok = 512;
            Q = q4; K = k4; V = v4; Yd = Y45; Ad = A45;
        } else {
            int b2 = bid - 256;
            bh = b2 >> 1; c = b2 & 1; ntok = 128;
            Q = q6; K = k6; V = v6; Yd = Y67; Ad = A67;
        }
        const size_t base = ((size_t)bh * ntok + (size_t)c * 64) * DD;

        {
            const int u = tid >> 4, cq = tid & 15, c4 = cq << 2;
            const float4* qf = (const float4*)(Q + base);
            const float4* kf = (const float4*)(K + base);
            const float4* vf = (const float4*)(V + base);
            const int i0 = (u << 6) + cq;
            float4 a0 = qf[i0], a1 = qf[i0 + 16], a2 = qf[i0 + 32], a3 = qf[i0 + 48];
            float4 b0 = kf[i0], b1 = kf[i0 + 16], b2 = kf[i0 + 32], b3 = kf[i0 + 48];
            float4 d0 = vf[i0], d1 = vf[i0 + 16], d2 = vf[i0 + 32], d3 = vf[i0 + 48];
            const int r0 = (u << 2) * SD + c4;
            *(float4*)(s_q0 + r0) = a0;           *(float4*)(s_q0 + r0 + SD) = a1;
            *(float4*)(s_q0 + r0 + 2 * SD) = a2;  *(float4*)(s_q0 + r0 + 3 * SD) = a3;
            *(float4*)(s_k0 + r0) = b0;           *(float4*)(s_k0 + r0 + SD) = b1;
            *(float4*)(s_k0 + r0 + 2 * SD) = b2;  *(float4*)(s_k0 + r0 + 3 * SD) = b3;
            *(float4*)(s_v0 + r0) = d0;           *(float4*)(s_v0 + r0 + SD) = d1;
            *(float4*)(s_v0 + r0 + 2 * SD) = d2;  *(float4*)(s_v0 + r0 + 3 * SD) = d3;
            const int r1 = (u << 1) * SD + c4;
            *(float4*)(s_q1 + r1) = f4_avg(a0, a1);  *(float4*)(s_q1 + r1 + SD) = f4_avg(a2, a3);
            *(float4*)(s_k1 + r1) = f4_avg(b0, b1);  *(float4*)(s_k1 + r1 + SD) = f4_avg(b2, b3);
            *(float4*)(s_v1 + r1) = f4_add(d0, d1);  *(float4*)(s_v1 + r1 + SD) = f4_add(d2, d3);
        }
        __syncthreads();

        u64 yp[16];
        float rs = 0.f;
        if (w < 4) {
            int sb = w ^ 1;
            rs = attn_block(s_q0 + w * 16 * SD, s_k0 + sb * 16 * SD,
                            s_v0 + sb * 16 * SD, i, dg, yp);
        } else if (w < 6) {
            int qb = w - 4, sb = qb ^ 1;
            rs = attn_block(s_q1 + qb * 16 * SD, s_k1 + sb * 16 * SD,
                            s_v1 + sb * 16 * SD, i, dg, yp);
            float* yo = s_y1 + (qb * 16 + i) * SD + (dg << 5);
#pragma unroll
            for (int cc = 0; cc < 8; cc++)
                *(ulonglong2*)(yo + cc * 4) = make_ulonglong2(yp[2 * cc], yp[2 * cc + 1]);
            if (dg == 0) s_a1[qb * 16 + i] = rs;
        }
        __syncthreads();

        if (w < 4) {
            const int r = (w << 4) + i;
            const float* y1r = s_y1 + (r >> 1) * SD + (dg << 5);
            float* yg = Yd + base + (size_t)r * DD + (dg << 5);
#pragma unroll
            for (int cc = 0; cc < 8; cc++) {
                ulonglong2 u1 = *(const ulonglong2*)(y1r + cc * 4);
                *(ulonglong2*)(yg + cc * 4) =
                    make_ulonglong2(add2(yp[2 * cc], u1.x), add2(yp[2 * cc + 1], u1.y));
            }
            if (dg == 0)
                Ad[bh * ntok + c * 64 + r] = rs + s_a1[r >> 1];
        }
    } else {
        const int bh = bid - 320;
        const size_t base = (size_t)bh * 32 * DD;
        const float4* qf = (const float4*)(q8 + base);
        const float4* kf = (const float4*)(k8 + base);
        const float4* vf = (const float4*)(v8 + base);
        for (int idx = tid; idx < 512; idx += 256) {
            int row = idx >> 4, c4 = (idx & 15) << 2;
            *(float4*)(s_q0 + row * SD + c4) = qf[idx];
            *(float4*)(s_k0 + row * SD + c4) = kf[idx];
            *(float4*)(s_v0 + row * SD + c4) = vf[idx];
        }
        __syncthreads();
        if (w < 2) {
            u64 yp[16];
            float rs = attn_block(s_q0 + w * 16 * SD, s_k0 + (w ^ 1) * 16 * SD,
                                  s_v0 + (w ^ 1) * 16 * SD, i, dg, yp);
            float* yg = Y8 + base + (size_t)((w << 4) + i) * DD + (dg << 5);
#pragma unroll
            for (int cc = 0; cc < 8; cc++)
                *(ulonglong2*)(yg + cc * 4) = make_ulonglong2(yp[2 * cc], yp[2 * cc + 1]);
            if (dg == 0) A8[bh * 32 + (w << 4) + i] = rs;
        }
    }
}

// ===========================================================================
// K_F: levels 0-1 + final combine. Warps 6/7 stage coarse Y/A into smem
// during the attention phase; Phase C sums all levels, divides, writes out.
// ===========================================================================
__global__ void __launch_bounds__(256, 2)
hatt_fused01(const float* __restrict__ Q, const float* __restrict__ K,
             const float* __restrict__ V, float* __restrict__ out,
             const float* __restrict__ Y23, const float* __restrict__ A23,
             const float* __restrict__ Y45, const float* __restrict__ A45,
             const float* __restrict__ Y67, const float* __restrict__ A67,
             const float* __restrict__ Y8, const float* __restrict__ A8)
{
    extern __shared__ float sm[];
    float* s_q0 = sm;                     // 64*SD
    float* s_k0 = s_q0 + 64 * SD;
    float* s_v0 = s_k0 + 64 * SD;
    float* s_q1 = s_v0 + 64 * SD;         // 32*SD
    float* s_k1 = s_q1 + 32 * SD;
    float* s_v1 = s_k1 + 32 * SD;
    float* s_y1 = s_v1 + 32 * SD;         // 32*SD
    float* s_a1 = s_y1 + 32 * SD;         // 32
    float* s_c = s_a1 + 32;               // 22*SD coarse Y stage
    float* s_ca = s_c + 22 * SD;          // 22 coarse A stage

    const int tid = threadIdx.x;
    const int bh = blockIdx.y;
    const int c = blockIdx.x;             // 0..127
    const size_t base = ((size_t)bh * N0 + (size_t)c * 64) * DD;

    // ---- Phase 1: load 64 orig rows (scaled q) + pool lvl1 locally ----
    {
        const int u = tid >> 4, cq = tid & 15, c4 = cq << 2;
        const float4* qf = (const float4*)(Q + base);
        const float4* kf = (const float4*)(K + base);
        const float4* vf = (const float4*)(V + base);
        const int i0 = (u << 6) + cq;
        float4 a0 = f4_scale(qf[i0], 0.125f), a1 = f4_scale(qf[i0 + 16], 0.125f);
        float4 a2 = f4_scale(qf[i0 + 32], 0.125f), a3 = f4_scale(qf[i0 + 48], 0.125f);
        float4 b0 = kf[i0], b1 = kf[i0 + 16], b2 = kf[i0 + 32], b3 = kf[i0 + 48];
        float4 d0 = vf[i0], d1 = vf[i0 + 16], d2 = vf[i0 + 32], d3 = vf[i0 + 48];
        const int r0 = (u << 2) * SD + c4;
        *(float4*)(s_q0 + r0) = a0;           *(float4*)(s_q0 + r0 + SD) = a1;
        *(float4*)(s_q0 + r0 + 2 * SD) = a2;  *(float4*)(s_q0 + r0 + 3 * SD) = a3;
        *(float4*)(s_k0 + r0) = b0;           *(float4*)(s_k0 + r0 + SD) = b1;
        *(float4*)(s_k0 + r0 + 2 * SD) = b2;  *(float4*)(s_k0 + r0 + 3 * SD) = b3;
        *(float4*)(s_v0 + r0) = d0;           *(float4*)(s_v0 + r0 + SD) = d1;
        *(float4*)(s_v0 + r0 + 2 * SD) = d2;  *(float4*)(s_v0 + r0 + 3 * SD) = d3;
        const int r1 = (u << 1) * SD + c4;
        *(float4*)(s_q1 + r1) = f4_avg(a0, a1);  *(float4*)(s_q1 + r1 + SD) = f4_avg(a2, a3);
        *(float4*)(s_k1 + r1) = f4_avg(b0, b1);  *(float4*)(s_k1 + r1 + SD) = f4_avg(b2, b3);
        *(float4*)(s_v1 + r1) = f4_add(d0, d1);  *(float4*)(s_v1 + r1 + SD) = f4_add(d2, d3);
    }
    __syncthreads();

    const int w = tid >> 5, lane = tid & 31, i = lane & 15, dg = lane >> 4;
    u64 yp[16];
    float rs = 0.f;
    if (w < 4) {
        // level 0: SELF-attention (no flip)
        rs = attn_block(s_q0 + w * 16 * SD, s_k0 + w * 16 * SD,
                        s_v0 + w * 16 * SD, i, dg, yp);
    } else if (w < 6) {
        int qb = w - 4, sb = qb ^ 1;
        rs = attn_block(s_q1 + qb * 16 * SD, s_k1 + sb * 16 * SD,
                        s_v1 + sb * 16 * SD, i, dg, yp);
        float* yo = s_y1 + (qb * 16 + i) * SD + (dg << 5);
#pragma unroll
        for (int cc = 0; cc < 8; cc++)
            *(ulonglong2*)(yo + cc * 4) = make_ulonglong2(yp[2 * cc], yp[2 * cc + 1]);
        if (dg == 0) s_a1[qb * 16 + i] = rs;
    } else if (w == 6) {
        // stage Y23: 16 rows (rows 0-15 of s_c)
        const float4* y23f = (const float4*)Y23;
#pragma unroll
        for (int it = 0; it < 8; it++) {
            int idx = (it << 5) + lane;
            int t = idx >> 4, cq = idx & 15;
            *(float4*)(s_c + t * SD + (cq << 2)) =
                y23f[((size_t)bh * 2048 + (size_t)c * 16 + t) * 16 + cq];
        }
    } else {
        // w==7: stage Y45 (rows 16-19), Y67 (20), Y8 (21), all coarse A's
        const float4* y45f = (const float4*)Y45;
#pragma unroll
        for (int it = 0; it < 2; it++) {
            int idx = (it << 5) + lane;
            int t = idx >> 4, cq = idx & 15;
            *(float4*)(s_c + (16 + t) * SD + (cq << 2)) =
                y45f[((size_t)bh * 512 + (size_t)c * 4 + t) * 16 + cq];
        }
        if (lane < 16) {
            *(float4*)(s_c + 20 * SD + (lane << 2)) =
                ((const float4*)Y67)[((size_t)bh * 128 + c) * 16 + lane];
            *(float4*)(s_c + 21 * SD + (lane << 2)) =
                ((const float4*)Y8)[((size_t)bh * 32 + (c >> 2)) * 16 + lane];
            s_ca[lane] = A23[bh * 2048 + c * 16 + lane];
        }
        if (lane < 4) s_ca[16 + lane] = A45[bh * 512 + c * 4 + lane];
        if (lane == 0) {
            s_ca[20] = A67[bh * 128 + c];
            s_ca[21] = A8[bh * 32 + (c >> 2)];
        }
    }
    __syncthreads();

    // ---- Phase C (w 0-3): sum all levels, divide, write out ----
    if (w < 4) {
        const int r = (w << 4) + i;
        float a = rs + s_a1[r >> 1] + s_ca[r >> 2] + s_ca[16 + (r >> 4)]
                + s_ca[20] + s_ca[21] + 1e-8f;
        float inv = 1.0f / a;
        u64 inv2 = pk2(inv, inv);
        const float* y1r = s_y1 + (r >> 1) * SD + (dg << 5);
        const float* c2p = s_c + (r >> 2) * SD + (dg << 5);
        const float* c4p = s_c + (16 + (r >> 4)) * SD + (dg << 5);
        const float* c6p = s_c + 20 * SD + (dg << 5);
        const float* c8p = s_c + 21 * SD + (dg << 5);
        float* yg = out + base + (size_t)r * DD + (dg << 5);
#pragma unroll
        for (int cc = 0; cc < 8; cc++) {
            ulonglong2 u1 = *(const ulonglong2*)(y1r + cc * 4);
            ulonglong2 u2 = *(const ulonglong2*)(c2p + cc * 4);
            ulonglong2 u4 = *(const ulonglong2*)(c4p + cc * 4);
            ulonglong2 u6 = *(const ulonglong2*)(c6p + cc * 4);
            ulonglong2 u8 = *(const ulonglong2*)(c8p + cc * 4);
            u64 sx = add2(add2(yp[2 * cc], u1.x),
                          add2(add2(u2.x, u4.x), add2(u6.x, u8.x)));
            u64 sy = add2(add2(yp[2 * cc + 1], u1.y),
                          add2(add2(u2.y, u4.y), add2(u6.y, u8.y)));
            *(ulonglong2*)(yg + cc * 4) = make_ulonglong2(mul2(sx, inv2), mul2(sy, inv2));
        }
    }
}

// ---------------------------------------------------------------------------
extern "C" void kernel_launch(void* const* d_in, const int* in_sizes, int n_in,
                              void* d_out, int out_size)
{
    const float* q = (const float*)d_in[0];
    const float* k = (const float*)d_in[1];
    const float* v = (const float*)d_in[2];
    float* out = (float*)d_out;
    (void)in_sizes; (void)n_in; (void)out_size;

    void *Y23, *A23, *q4, *k4, *v4, *Y45, *A45, *q6, *k6, *v6, *Y67, *A67;
    void *q8, *k8, *v8, *Y8, *A8;
    cudaGetSymbolAddress(&Y23, g_Y23);
    cudaGetSymbolAddress(&A23, g_A23);
    cudaGetSymbolAddress(&q4, g_q4);
    cudaGetSymbolAddress(&k4, g_k4);
    cudaGetSymbolAddress(&v4, g_v4);
    cudaGetSymbolAddress(&Y45, g_Y45);
    cudaGetSymbolAddress(&A45, g_A45);
    cudaGetSymbolAddress(&q6, g_q6);
    cudaGetSymbolAddress(&k6, g_k6);
    cudaGetSymbolAddress(&v6, g_v6);
    cudaGetSymbolAddress(&Y67, g_Y67);
    cudaGetSymbolAddress(&A67, g_A67);
    cudaGetSymbolAddress(&q8, g_q8);
    cudaGetSymbolAddress(&k8, g_k8);
    cudaGetSymbolAddress(&v8, g_v8);
    cudaGetSymbolAddress(&Y8, g_Y8);
    cudaGetSymbolAddress(&A8, g_A8);

    const int S23 = (64 * SD * 3 + 32 * SD * 4 + 32 + 16 * SD * 3) * (int)sizeof(float); // 100224
    const int ST  = (64 * SD * 3 + 32 * SD * 4 + 32) * (int)sizeof(float);               // 87168
    const int SF  = (64 * SD * 3 + 32 * SD * 4 + 32 + 22 * SD + 22) * (int)sizeof(float);// 93240
    cudaFuncSetAttribute(hatt_lvl23, cudaFuncAttributeMaxDynamicSharedMemorySize, S23);
    cudaFuncSetAttribute(hatt_tail, cudaFuncAttributeMaxDynamicSharedMemorySize, ST);
    cudaFuncSetAttribute(hatt_fused01, cudaFuncAttributeMaxDynamicSharedMemorySize, SF);

    // K_A: levels 2-3 from original (pool x4 in regs) + pooled lvl4/6/8 out.
    hatt_lvl23<<<dim3(32, 32), 256, S23>>>(
        q, k, v, (float*)Y23, (float*)A23,
        (float*)q4, (float*)k4, (float*)v4,
        (float*)q6, (float*)k6, (float*)v6,
        (float*)q8, (float*)k8, (float*)v8);

    // K_T: fused tail (levels 4-5, 6-7, 8) in one launch.
    hatt_tail<<<352, 256, ST>>>(
        (const float*)q4, (const float*)k4, (const float*)v4, (float*)Y45, (float*)A45,
        (const float*)q6, (const float*)k6, (const float*)v6, (float*)Y67, (float*)A67,
        (const float*)q8, (const float*)k8, (const float*)v8, (float*)Y8, (float*)A8);

    // K_F: levels 0-1 + combine + divide -> out.
    hatt_fused01<<<dim3(128, 32), 256, SF>>>(
        q, k, v, out,
        (const float*)Y23, (const float*)A23, (const float*)Y45, (const float*)A45,
        (const float*)Y67, (const float*)A67, (const float*)Y8, (const float*)A8);
}